// round 5
// baseline (speedup 1.0000x reference)
#include <cuda_runtime.h>
#include <cstdint>

#define B 1024
#define T 128
#define INP 5
#define H 100
#define G4 400   // 4*H

// ---------------- scratch (device globals; no runtime allocation) ----------
__device__ float g_h0 [B * T * 2 * H];   // [b][t][200]  layer0 output (fwd|bwd)
__device__ float g_xg1[B * T * G4];      // [b*T+t][400] layer1-fwd input gates (+biases)
__device__ float g_h1f[B * H];           // layer1-fwd final hidden

typedef unsigned long long u64;

// ---------------- packed fp32x2 helpers ------------------------------------
__device__ __forceinline__ u64 pk2(float a, float b) {
    u64 r; asm("mov.b64 %0, {%1,%2};" : "=l"(r) : "f"(a), "f"(b)); return r;
}
__device__ __forceinline__ void upk2(u64 v, float& a, float& b) {
    asm("mov.b64 {%0,%1}, %2;" : "=f"(a), "=f"(b) : "l"(v));
}
__device__ __forceinline__ u64 ffma2(u64 a, u64 b, u64 c) {
    asm("fma.rn.f32x2 %0, %1, %2, %0;" : "+l"(c) : "l"(a), "l"(b)); return c;
}

// ---------------- fast activations (ex2.approx + rcp.approx, ~1e-6 err) ----
__device__ __forceinline__ float fsig(float x) {
    float e; asm("ex2.approx.f32 %0, %1;" : "=f"(e) : "f"(x * -1.4426950408889634f));
    float r; asm("rcp.approx.f32 %0, %1;" : "=f"(r) : "f"(e + 1.0f));
    return r;
}
__device__ __forceinline__ float ftanh_(float x) {
    float e; asm("ex2.approx.f32 %0, %1;" : "=f"(e) : "f"(x * -2.885390081777927f));
    float r; asm("rcp.approx.f32 %0, %1;" : "=f"(r) : "f"(e + 1.0f));
    return fmaf(2.0f, r, -1.0f);
}

// ============================================================================
// Kernel 1: layer0, both directions. grid=128 (dir*64+chunk), block=256.
// 16 batch rows/CTA, W_hh^T resident in SMEM, double-buffered h & x,
// ONE __syncthreads per step.  (unchanged from R4 — at FFMA2 floor)
// ============================================================================
#define L0_NB    16
#define L0_PAIRS 8
#define L0_PAD   9
#define L0_HBUF  (100*L0_PAD*2)          // 1800 floats per buffer
#define L0_XBUF  (INP*L0_PAIRS*2)        // 80 floats per buffer
#define L0_SMEMF (40000 + 2000 + 400 + 2*L0_HBUF + 2*L0_XBUF)

__global__ void __launch_bounds__(256, 1) lstm_layer0(
    const float* __restrict__ x,
    const float* __restrict__ wih_f, const float* __restrict__ whh_f,
    const float* __restrict__ bih_f, const float* __restrict__ bhh_f,
    const float* __restrict__ wih_b, const float* __restrict__ whh_b,
    const float* __restrict__ bih_b, const float* __restrict__ bhh_b)
{
    extern __shared__ float sm[];
    float* whh_t = sm;                          // [100][400] (k-major)
    float* wihT  = sm + 40000;                  // [5][400]
    float* bias  = sm + 42000;                  // [400]
    float* h2f   = sm + 42400;                  // 2 buffers, float2 [100][9]
    float* x2f   = sm + 42400 + 2*L0_HBUF;      // 2 buffers, float2 [5][8]

    const int tid = threadIdx.x;
    const int dir = blockIdx.x >> 6;
    const int b0  = (blockIdx.x & 63) * L0_NB;
    const float* wih = dir ? wih_b : wih_f;
    const float* whh = dir ? whh_b : whh_f;
    const float* bih = dir ? bih_b : bih_f;
    const float* bhh = dir ? bhh_b : bhh_f;

    for (int i = tid; i < 40000; i += 256) {
        int g = i / 100, k = i - g * 100;
        whh_t[k * 400 + g] = whh[i];
    }
    for (int i = tid; i < 2000; i += 256) {
        int g = i / 5, d = i - g * 5;
        wihT[d * 400 + g] = wih[i];
    }
    for (int i = tid; i < 400; i += 256) bias[i] = bih[i] + bhh[i];
    for (int i = tid; i < L0_HBUF; i += 256) h2f[i] = 0.f;   // buffer 0 only

    {
        int t0 = dir ? (T - 1) : 0;
        if (tid < L0_NB * INP) {
            int bl = tid / INP, d = tid - bl * INP;
            x2f[(d * L0_PAIRS + (bl >> 1)) * 2 + (bl & 1)] =
                x[((size_t)(b0 + bl) * T + t0) * INP + d];
        }
    }

    const int  jj  = tid & 127;
    const int  grp = tid >> 7;
    const bool act = (jj < H);
    float c_reg[8];
    #pragma unroll
    for (int i = 0; i < 8; i++) c_reg[i] = 0.f;

    __syncthreads();

    for (int ts = 0; ts < T; ts++) {
        const int t   = dir ? (T - 1 - ts) : ts;
        const int cur = ts & 1, nxt = cur ^ 1;
        const u64* h2u = (const u64*)(h2f + cur * L0_HBUF);
        const u64* x2u = (const u64*)(x2f + cur * L0_XBUF);

        u64 acc[4][4];
        if (act) {
            #pragma unroll
            for (int g = 0; g < 4; g++) {
                float bv = bias[g * 100 + jj];
                u64 b2 = pk2(bv, bv);
                #pragma unroll
                for (int p = 0; p < 4; p++) acc[p][g] = b2;
            }
            #pragma unroll
            for (int d = 0; d < INP; d++) {
                const float* wr = wihT + d * 400 + jj;
                u64 w0 = pk2(wr[0], wr[0]),     w1 = pk2(wr[100], wr[100]);
                u64 w2 = pk2(wr[200], wr[200]), w3 = pk2(wr[300], wr[300]);
                #pragma unroll
                for (int p = 0; p < 4; p++) {
                    u64 xv = x2u[d * L0_PAIRS + grp * 4 + p];
                    acc[p][0] = ffma2(w0, xv, acc[p][0]);
                    acc[p][1] = ffma2(w1, xv, acc[p][1]);
                    acc[p][2] = ffma2(w2, xv, acc[p][2]);
                    acc[p][3] = ffma2(w3, xv, acc[p][3]);
                }
            }
            #pragma unroll 4
            for (int k = 0; k < H; k++) {
                const float* wr = whh_t + k * 400 + jj;
                u64 w0 = pk2(wr[0], wr[0]),     w1 = pk2(wr[100], wr[100]);
                u64 w2 = pk2(wr[200], wr[200]), w3 = pk2(wr[300], wr[300]);
                const u64* hr = h2u + k * L0_PAD + grp * 4;
                #pragma unroll
                for (int p = 0; p < 4; p++) {
                    u64 hv = hr[p];
                    acc[p][0] = ffma2(w0, hv, acc[p][0]);
                    acc[p][1] = ffma2(w1, hv, acc[p][1]);
                    acc[p][2] = ffma2(w2, hv, acc[p][2]);
                    acc[p][3] = ffma2(w3, hv, acc[p][3]);
                }
            }
        }

        if (ts + 1 < T && tid < L0_NB * INP) {
            int tn = dir ? (T - 2 - ts) : (ts + 1);
            int bl = tid / INP, d = tid - bl * INP;
            x2f[nxt * L0_XBUF + (d * L0_PAIRS + (bl >> 1)) * 2 + (bl & 1)] =
                x[((size_t)(b0 + bl) * T + tn) * INP + d];
        }

        if (act) {
            float2* hw = (float2*)(h2f + nxt * L0_HBUF);
            #pragma unroll
            for (int p = 0; p < 4; p++) {
                float i0, i1, f0, f1, g0, g1, o0, o1;
                upk2(acc[p][0], i0, i1); upk2(acc[p][1], f0, f1);
                upk2(acc[p][2], g0, g1); upk2(acc[p][3], o0, o1);
                int P = grp * 4 + p;
                float c0 = c_reg[2 * p],     c1 = c_reg[2 * p + 1];
                c0 = fsig(f0) * c0 + fsig(i0) * ftanh_(g0);
                c1 = fsig(f1) * c1 + fsig(i1) * ftanh_(g1);
                float hv0 = fsig(o0) * ftanh_(c0);
                float hv1 = fsig(o1) * ftanh_(c1);
                c_reg[2 * p] = c0; c_reg[2 * p + 1] = c1;
                hw[jj * L0_PAD + P] = make_float2(hv0, hv1);
                int be = b0 + 2 * P;
                g_h0[((size_t)be * T + t) * 200 + dir * 100 + jj]       = hv0;
                g_h0[((size_t)(be + 1) * T + t) * 200 + dir * 100 + jj] = hv1;
            }
        }
        __syncthreads();   // single barrier per step
    }
}

// ============================================================================
// Kernel 2: xg1 = h0 @ W_ih_l1f^T + (b_ih+b_hh).  M=131072, K=200, N=400.
// grid (5, 1024): n-tile varies FASTEST so the 5 CTAs sharing one A m-tile
// run adjacently -> A read from DRAM once (L2 reuse). 2 CTAs/SM pinned.
// ============================================================================
__global__ void __launch_bounds__(256, 2) gemm_xg1_kernel(
    const float* __restrict__ wih,
    const float* __restrict__ bih, const float* __restrict__ bhh)
{
    __shared__ float As[2][8][132];
    __shared__ float Bs[2][8][84];
    const int tid = threadIdx.x;
    const int n0 = blockIdx.x * 80;      // x = n-tile (fastest)
    const int m0 = blockIdx.y * 128;     // y = m-tile
    const int tx = tid & 15, ty = tid >> 4;
    const int arow = tid >> 1, aseg = tid & 1;
    const int brow = tid >> 1, bseg = tid & 1;

    u64 acc[4][5];
    #pragma unroll
    for (int i = 0; i < 4; i++)
        #pragma unroll
        for (int n = 0; n < 5; n++) acc[i][n] = pk2(0.f, 0.f);

    // preload tile 0
    float4 av = *(const float4*)(g_h0 + (size_t)(m0 + arow) * 200 + aseg * 4);
    float4 bv = make_float4(0.f, 0.f, 0.f, 0.f);
    if (tid < 160)
        bv = *(const float4*)(wih + (size_t)(n0 + brow) * 200 + bseg * 4);
    As[0][aseg * 4 + 0][arow] = av.x; As[0][aseg * 4 + 1][arow] = av.y;
    As[0][aseg * 4 + 2][arow] = av.z; As[0][aseg * 4 + 3][arow] = av.w;
    if (tid < 160) {
        Bs[0][bseg * 4 + 0][brow] = bv.x; Bs[0][bseg * 4 + 1][brow] = bv.y;
        Bs[0][bseg * 4 + 2][brow] = bv.z; Bs[0][bseg * 4 + 3][brow] = bv.w;
    }
    __syncthreads();

    for (int kt = 0; kt < 25; kt++) {
        const int cur = kt & 1, nx = cur ^ 1;
        if (kt < 24) {
            int k0 = (kt + 1) * 8;
            av = *(const float4*)(g_h0 + (size_t)(m0 + arow) * 200 + k0 + aseg * 4);
            if (tid < 160)
                bv = *(const float4*)(wih + (size_t)(n0 + brow) * 200 + k0 + bseg * 4);
        }
        #pragma unroll
        for (int kk = 0; kk < 8; kk++) {
            u64 a2[4];
            #pragma unroll
            for (int i = 0; i < 4; i++)
                a2[i] = *(const u64*)&As[cur][kk][ty * 8 + 2 * i];
            #pragma unroll
            for (int n = 0; n < 5; n++) {
                float bb = Bs[cur][kk][tx * 5 + n];
                u64 b2 = pk2(bb, bb);
                #pragma unroll
                for (int i = 0; i < 4; i++) acc[i][n] = ffma2(a2[i], b2, acc[i][n]);
            }
        }
        if (kt < 24) {
            As[nx][aseg * 4 + 0][arow] = av.x; As[nx][aseg * 4 + 1][arow] = av.y;
            As[nx][aseg * 4 + 2][arow] = av.z; As[nx][aseg * 4 + 3][arow] = av.w;
            if (tid < 160) {
                Bs[nx][bseg * 4 + 0][brow] = bv.x; Bs[nx][bseg * 4 + 1][brow] = bv.y;
                Bs[nx][bseg * 4 + 2][brow] = bv.z; Bs[nx][bseg * 4 + 3][brow] = bv.w;
            }
            __syncthreads();
        }
    }
    #pragma unroll
    for (int n = 0; n < 5; n++) {
        int gn = n0 + tx * 5 + n;
        float bvv = bih[gn] + bhh[gn];
        #pragma unroll
        for (int i = 0; i < 4; i++) {
            float v0, v1; upk2(acc[i][n], v0, v1);
            int m = m0 + ty * 8 + 2 * i;
            g_xg1[(size_t)m * 400 + gn]       = v0 + bvv;
            g_xg1[(size_t)(m + 1) * 400 + gn] = v1 + bvv;
        }
    }
}

// ============================================================================
// Kernel 3: layer1 forward recurrence; only final h kept. (unchanged)
// ============================================================================
#define L1_NB   8
#define L1_PAD  5
#define L1_HBUF (100*L1_PAD*2)
#define L1_SMEMF (40000 + 2*L1_HBUF)

__global__ void __launch_bounds__(256, 1) lstm_layer1f(const float* __restrict__ whh)
{
    extern __shared__ float sm[];
    float* whh_t = sm;              // [100][400]
    float* h2f   = sm + 40000;      // 2 buffers float2 [100][5]
    const int tid = threadIdx.x;
    const int b0 = blockIdx.x * L1_NB;

    for (int i = tid; i < 40000; i += 256) {
        int g = i / 100, k = i - g * 100;
        whh_t[k * 400 + g] = whh[i];
    }
    for (int i = tid; i < L1_HBUF; i += 256) h2f[i] = 0.f;   // buffer 0

    const int  jj  = tid & 127;
    const int  grp = tid >> 7;
    const bool act = (jj < H);
    float c_reg[4] = {0.f, 0.f, 0.f, 0.f};

    float xr[2][4][2];
    if (act) {
        #pragma unroll
        for (int p = 0; p < 2; p++) {
            int P = grp * 2 + p;
            const float* xga = g_xg1 + ((size_t)(b0 + 2 * P) * T + 0) * 400 + jj;
            const float* xgb = xga + (size_t)T * 400;
            #pragma unroll
            for (int g = 0; g < 4; g++) { xr[p][g][0] = xga[g * 100]; xr[p][g][1] = xgb[g * 100]; }
        }
    }

    __syncthreads();

    for (int t = 0; t < T; t++) {
        const int cur = t & 1, nxt = cur ^ 1;
        const u64* h2u = (const u64*)(h2f + cur * L1_HBUF);

        u64 acc[2][4];
        if (act) {
            #pragma unroll
            for (int p = 0; p < 2; p++)
                #pragma unroll
                for (int g = 0; g < 4; g++)
                    acc[p][g] = pk2(xr[p][g][0], xr[p][g][1]);

            if (t + 1 < T) {
                #pragma unroll
                for (int p = 0; p < 2; p++) {
                    int P = grp * 2 + p;
                    const float* xga = g_xg1 + ((size_t)(b0 + 2 * P) * T + (t + 1)) * 400 + jj;
                    const float* xgb = xga + (size_t)T * 400;
                    #pragma unroll
                    for (int g = 0; g < 4; g++) { xr[p][g][0] = xga[g * 100]; xr[p][g][1] = xgb[g * 100]; }
                }
            }

            #pragma unroll 4
            for (int k = 0; k < H; k++) {
                const float* wr = whh_t + k * 400 + jj;
                u64 w0 = pk2(wr[0], wr[0]),     w1 = pk2(wr[100], wr[100]);
                u64 w2 = pk2(wr[200], wr[200]), w3 = pk2(wr[300], wr[300]);
                const u64* hr = h2u + k * L1_PAD + grp * 2;
                #pragma unroll
                for (int p = 0; p < 2; p++) {
                    u64 hv = hr[p];
                    acc[p][0] = ffma2(w0, hv, acc[p][0]);
                    acc[p][1] = ffma2(w1, hv, acc[p][1]);
                    acc[p][2] = ffma2(w2, hv, acc[p][2]);
                    acc[p][3] = ffma2(w3, hv, acc[p][3]);
                }
            }

            float2* hw = (float2*)(h2f + nxt * L1_HBUF);
            #pragma unroll
            for (int p = 0; p < 2; p++) {
                float i0, i1, f0, f1, g0, g1, o0, o1;
                upk2(acc[p][0], i0, i1); upk2(acc[p][1], f0, f1);
                upk2(acc[p][2], g0, g1); upk2(acc[p][3], o0, o1);
                int P = grp * 2 + p;
                float c0 = c_reg[2 * p],     c1 = c_reg[2 * p + 1];
                c0 = fsig(f0) * c0 + fsig(i0) * ftanh_(g0);
                c1 = fsig(f1) * c1 + fsig(i1) * ftanh_(g1);
                float hv0 = fsig(o0) * ftanh_(c0);
                float hv1 = fsig(o1) * ftanh_(c1);
                c_reg[2 * p] = c0; c_reg[2 * p + 1] = c1;
                hw[jj * L1_PAD + P] = make_float2(hv0, hv1);
                if (t == T - 1) {
                    int be = b0 + 2 * P;
                    g_h1f[(size_t)be * 100 + jj]       = hv0;
                    g_h1f[(size_t)(be + 1) * 100 + jj] = hv1;
                }
            }
        }
        __syncthreads();
    }
}

// ============================================================================
// Kernel 4 (REWRITTEN): layer1 backward single step (c0=0 -> f-gate dead,
// only i,g,o needed) + FC + softmax. grid=64, 16 batches/CTA, f32x2 packed.
// smem floats: WT 30000 | H0 200*18 | H1B 1600 | B3 300 | FCW 600 | FCB 4 | LG 48
// ============================================================================
#define FN_SMEMF (30000 + 200*18 + 1600 + 300 + 600 + 4 + 48)

__global__ void __launch_bounds__(256, 1) lstm_final(
    const float* __restrict__ wih1b,
    const float* __restrict__ bih1b, const float* __restrict__ bhh1b,
    const float* __restrict__ fc_w,  const float* __restrict__ fc_b,
    float* __restrict__ out)
{
    extern __shared__ float sm[];
    float* wT   = sm;                  // [100 k][300 = {i,g,o}x100j] per k-tile
    float* h0s  = sm + 30000;          // [200 k][18]  (16 batches + pad 2)
    float* h1bs = sm + 30000 + 3600;   // [16][100]
    float* b3   = sm + 35200;          // [300] combined bias for i,g,o
    float* fcw  = sm + 35500;          // [600]
    float* fcb  = sm + 36100;          // [4]
    float* lg   = sm + 36104;          // [48]

    const int tid = threadIdx.x;
    const int b0 = blockIdx.x * 16;

    // h0 at t=T-1, batch-pair-packed per k row (coalesced LDG)
    for (int i = tid; i < 16 * 200; i += 256) {
        int b = i / 200, k = i - b * 200;
        h0s[k * 18 + b] = g_h0[((size_t)(b0 + b) * T + (T - 1)) * 200 + k];
    }
    for (int i = tid; i < 300; i += 256) {
        int g3 = i / 100, j = i - g3 * 100;
        int row = j + (g3 == 0 ? 0 : (g3 == 1 ? 200 : 300));
        b3[i] = bih1b[row] + bhh1b[row];
    }
    for (int i = tid; i < 600; i += 256) fcw[i] = fc_w[i];
    if (tid < 3) fcb[tid] = fc_b[tid];

    const int  jj  = tid & 127;
    const int  grp = tid >> 7;
    const bool act = (jj < H);

    u64 acc[4][3];
    #pragma unroll
    for (int p = 0; p < 4; p++)
        #pragma unroll
        for (int g = 0; g < 3; g++) acc[p][g] = pk2(0.f, 0.f);

    for (int kt = 0; kt < 2; kt++) {
        __syncthreads();
        // stage k-tile of W (gates i,g,o only), transposed to [k][3*100]
        for (int i = tid; i < 30000; i += 256) {
            int k = i % 100, j100 = i / 100;
            int grow = j100 + (j100 >= 100 ? 100 : 0);   // 0..99->i, 100..199->g, 200..299->o
            wT[k * 300 + j100] = wih1b[(size_t)grow * 200 + kt * 100 + k];
        }
        __syncthreads();
        if (act) {
            #pragma unroll 2
            for (int k = 0; k < 100; k++) {
                const float* wr = wT + k * 300 + jj;
                u64 w0 = pk2(wr[0], wr[0]);
                u64 w1 = pk2(wr[100], wr[100]);
                u64 w2 = pk2(wr[200], wr[200]);
                const float* hb = h0s + (kt * 100 + k) * 18 + grp * 8;
                #pragma unroll
                for (int p = 0; p < 4; p++) {
                    u64 hv = *(const u64*)(hb + 2 * p);
                    acc[p][0] = ffma2(w0, hv, acc[p][0]);
                    acc[p][1] = ffma2(w1, hv, acc[p][1]);
                    acc[p][2] = ffma2(w2, hv, acc[p][2]);
                }
            }
        }
    }
    if (act) {
        #pragma unroll
        for (int p = 0; p < 4; p++) {
            float i0, i1, g0, g1, o0, o1;
            upk2(acc[p][0], i0, i1);
            upk2(acc[p][1], g0, g1);
            upk2(acc[p][2], o0, o1);
            float bi = b3[jj], bg = b3[100 + jj], bo = b3[200 + jj];
            i0 += bi; i1 += bi; g0 += bg; g1 += bg; o0 += bo; o1 += bo;
            float c0 = fsig(i0) * ftanh_(g0);
            float c1 = fsig(i1) * ftanh_(g1);
            int bl = grp * 8 + 2 * p;
            h1bs[bl * 100 + jj]       = fsig(o0) * ftanh_(c0);
            h1bs[(bl + 1) * 100 + jj] = fsig(o1) * ftanh_(c1);
        }
    }
    __syncthreads();
    if (tid < 48) {
        int b = tid / 3, cls = tid - b * 3;
        float a = fcb[cls];
        const float* h1f = g_h1f + (size_t)(b0 + b) * 100;
        #pragma unroll 4
        for (int j = 0; j < 100; j++) {
            a += h1f[j]            * fcw[cls * 200 + j];
            a += h1bs[b * 100 + j] * fcw[cls * 200 + 100 + j];
        }
        lg[tid] = a;
    }
    __syncthreads();
    if (tid < 16) {
        int b = tid;
        float l0 = lg[b * 3], l1 = lg[b * 3 + 1], l2 = lg[b * 3 + 2];
        float m = fmaxf(l0, fmaxf(l1, l2));
        float e0 = __expf(l0 - m), e1 = __expf(l1 - m), e2 = __expf(l2 - m);
        float s = 1.0f / (e0 + e1 + e2);
        out[(b0 + b) * 3 + 0] = e0 * s;
        out[(b0 + b) * 3 + 1] = e1 * s;
        out[(b0 + b) * 3 + 2] = e2 * s;
    }
}

// ============================================================================
extern "C" void kernel_launch(void* const* d_in, const int* in_sizes, int n_in,
                              void* d_out, int out_size)
{
    (void)in_sizes; (void)n_in; (void)out_size;
    const float* x     = (const float*)d_in[0];
    const float* wih0f = (const float*)d_in[1];
    const float* whh0f = (const float*)d_in[2];
    const float* bih0f = (const float*)d_in[3];
    const float* bhh0f = (const float*)d_in[4];
    const float* wih0b = (const float*)d_in[5];
    const float* whh0b = (const float*)d_in[6];
    const float* bih0b = (const float*)d_in[7];
    const float* bhh0b = (const float*)d_in[8];
    const float* wih1f = (const float*)d_in[9];
    const float* whh1f = (const float*)d_in[10];
    const float* bih1f = (const float*)d_in[11];
    const float* bhh1f = (const float*)d_in[12];
    const float* wih1b = (const float*)d_in[13];
    const float* bih1b = (const float*)d_in[15];
    const float* bhh1b = (const float*)d_in[16];
    const float* fcw   = (const float*)d_in[17];
    const float* fcb   = (const float*)d_in[18];
    float* out = (float*)d_out;

    const int sm0 = L0_SMEMF * 4;
    const int sm1 = L1_SMEMF * 4;
    const int sm2 = FN_SMEMF * 4;
    cudaFuncSetAttribute(lstm_layer0,  cudaFuncAttributeMaxDynamicSharedMemorySize, sm0);
    cudaFuncSetAttribute(lstm_layer1f, cudaFuncAttributeMaxDynamicSharedMemorySize, sm1);
    cudaFuncSetAttribute(lstm_final,   cudaFuncAttributeMaxDynamicSharedMemorySize, sm2);

    lstm_layer0<<<128, 256, sm0>>>(x, wih0f, whh0f, bih0f, bhh0f,
                                      wih0b, whh0b, bih0b, bhh0b);
    gemm_xg1_kernel<<<dim3(5, 1024), 256>>>(wih1f, bih1f, bhh1f);
    lstm_layer1f<<<128, 256, sm1>>>(whh1f);
    lstm_final<<<64, 256, sm2>>>(wih1b, bih1b, bhh1b, fcw, fcb, out);
}

// round 7
// speedup vs baseline: 1.0732x; 1.0732x over previous
#include <cuda_runtime.h>
#include <cuda_bf16.h>
#include <cstdint>

#define B 1024
#define T 128
#define INP 5
#define H 100
#define G4 400    // 4*H
#define MTOT (B*T)        // 131072 GEMM rows
#define KPAD 208          // 200 padded to 16-multiple

// ---------------- scratch (device globals; no runtime allocation) ----------
__device__ float g_h0s[B * 2 * H];            // [b][200] h0 at t=T-1 only
__device__ float g_xg1[(size_t)MTOT * G4];    // [t*B+b][400] layer1-fwd gates (+bias)
__device__ float g_h1f[B * H];                // layer1-fwd final hidden
// bf16 split GEMM operands, layout [t*B+b][KPAD]; pad cols 200..207 stay 0
// (.bss zero-init, never written)
__device__ __nv_bfloat16 g_Ah[(size_t)MTOT * KPAD];
__device__ __nv_bfloat16 g_Al[(size_t)MTOT * KPAD];
__device__ __nv_bfloat16 g_Bh[400 * KPAD];
__device__ __nv_bfloat16 g_Bl[400 * KPAD];

typedef unsigned long long u64;

// ---------------- packed fp32x2 helpers ------------------------------------
__device__ __forceinline__ u64 pk2(float a, float b) {
    u64 r; asm("mov.b64 %0, {%1,%2};" : "=l"(r) : "f"(a), "f"(b)); return r;
}
__device__ __forceinline__ void upk2(u64 v, float& a, float& b) {
    asm("mov.b64 {%0,%1}, %2;" : "=f"(a), "=f"(b) : "l"(v));
}
__device__ __forceinline__ u64 ffma2(u64 a, u64 b, u64 c) {
    asm("fma.rn.f32x2 %0, %1, %2, %0;" : "+l"(c) : "l"(a), "l"(b)); return c;
}

// ---------------- fast activations ------------------------------------------
__device__ __forceinline__ float fsig(float x) {
    float e; asm("ex2.approx.f32 %0, %1;" : "=f"(e) : "f"(x * -1.4426950408889634f));
    float r; asm("rcp.approx.f32 %0, %1;" : "=f"(r) : "f"(e + 1.0f));
    return r;
}
__device__ __forceinline__ float ftanh_(float x) {
    float e; asm("ex2.approx.f32 %0, %1;" : "=f"(e) : "f"(x * -2.885390081777927f));
    float r; asm("rcp.approx.f32 %0, %1;" : "=f"(r) : "f"(e + 1.0f));
    return fmaf(2.0f, r, -1.0f);
}

__device__ __forceinline__ uint32_t smem_u32(const void* p) {
    uint32_t a;
    asm("{ .reg .u64 t; cvta.to.shared.u64 t, %1; cvt.u32.u64 %0, t; }" : "=r"(a) : "l"(p));
    return a;
}

// ============================================================================
// Kernel 1: layer0, both directions. grid=128, block=256, 16 batches/CTA.
// Emits bf16 hi/lo h0 in [t*B+b][KPAD] layout (coalesced stores) and fp32
// h0 at t=T-1 for lstm_final.
// ============================================================================
#define L0_NB    16
#define L0_PAIRS 8
#define L0_PAD   9
#define L0_HBUF  (100*L0_PAD*2)
#define L0_XBUF  (INP*L0_PAIRS*2)
#define L0_SMEMF (40000 + 2000 + 400 + 2*L0_HBUF + 2*L0_XBUF)

__global__ void __launch_bounds__(256, 1) lstm_layer0(
    const float* __restrict__ x,
    const float* __restrict__ wih_f, const float* __restrict__ whh_f,
    const float* __restrict__ bih_f, const float* __restrict__ bhh_f,
    const float* __restrict__ wih_b, const float* __restrict__ whh_b,
    const float* __restrict__ bih_b, const float* __restrict__ bhh_b)
{
    extern __shared__ float sm[];
    float* whh_t = sm;                          // [100][400]
    float* wihT  = sm + 40000;                  // [5][400]
    float* bias  = sm + 42000;                  // [400]
    float* h2f   = sm + 42400;                  // 2 buffers float2 [100][9]
    float* x2f   = sm + 42400 + 2*L0_HBUF;      // 2 buffers float2 [5][8]

    const int tid = threadIdx.x;
    const int dir = blockIdx.x >> 6;
    const int b0  = (blockIdx.x & 63) * L0_NB;
    const float* wih = dir ? wih_b : wih_f;
    const float* whh = dir ? whh_b : whh_f;
    const float* bih = dir ? bih_b : bih_f;
    const float* bhh = dir ? bhh_b : bhh_f;

    for (int i = tid; i < 40000; i += 256) {
        int g = i / 100, k = i - g * 100;
        whh_t[k * 400 + g] = whh[i];
    }
    for (int i = tid; i < 2000; i += 256) {
        int g = i / 5, d = i - g * 5;
        wihT[d * 400 + g] = wih[i];
    }
    for (int i = tid; i < 400; i += 256) bias[i] = bih[i] + bhh[i];
    for (int i = tid; i < L0_HBUF; i += 256) h2f[i] = 0.f;

    {
        int t0 = dir ? (T - 1) : 0;
        if (tid < L0_NB * INP) {
            int bl = tid / INP, d = tid - bl * INP;
            x2f[(d * L0_PAIRS + (bl >> 1)) * 2 + (bl & 1)] =
                x[((size_t)(b0 + bl) * T + t0) * INP + d];
        }
    }

    const int  jj  = tid & 127;
    const int  grp = tid >> 7;
    const bool act = (jj < H);
    float c_reg[8];
    #pragma unroll
    for (int i = 0; i < 8; i++) c_reg[i] = 0.f;

    __syncthreads();

    for (int ts = 0; ts < T; ts++) {
        const int t   = dir ? (T - 1 - ts) : ts;
        const int cur = ts & 1, nxt = cur ^ 1;
        const u64* h2u = (const u64*)(h2f + cur * L0_HBUF);
        const u64* x2u = (const u64*)(x2f + cur * L0_XBUF);

        u64 acc[4][4];
        if (act) {
            #pragma unroll
            for (int g = 0; g < 4; g++) {
                float bv = bias[g * 100 + jj];
                u64 b2 = pk2(bv, bv);
                #pragma unroll
                for (int p = 0; p < 4; p++) acc[p][g] = b2;
            }
            #pragma unroll
            for (int d = 0; d < INP; d++) {
                const float* wr = wihT + d * 400 + jj;
                u64 w0 = pk2(wr[0], wr[0]),     w1 = pk2(wr[100], wr[100]);
                u64 w2 = pk2(wr[200], wr[200]), w3 = pk2(wr[300], wr[300]);
                #pragma unroll
                for (int p = 0; p < 4; p++) {
                    u64 xv = x2u[d * L0_PAIRS + grp * 4 + p];
                    acc[p][0] = ffma2(w0, xv, acc[p][0]);
                    acc[p][1] = ffma2(w1, xv, acc[p][1]);
                    acc[p][2] = ffma2(w2, xv, acc[p][2]);
                    acc[p][3] = ffma2(w3, xv, acc[p][3]);
                }
            }
            #pragma unroll 4
            for (int k = 0; k < H; k++) {
                const float* wr = whh_t + k * 400 + jj;
                u64 w0 = pk2(wr[0], wr[0]),     w1 = pk2(wr[100], wr[100]);
                u64 w2 = pk2(wr[200], wr[200]), w3 = pk2(wr[300], wr[300]);
                const u64* hr = h2u + k * L0_PAD + grp * 4;
                #pragma unroll
                for (int p = 0; p < 4; p++) {
                    u64 hv = hr[p];
                    acc[p][0] = ffma2(w0, hv, acc[p][0]);
                    acc[p][1] = ffma2(w1, hv, acc[p][1]);
                    acc[p][2] = ffma2(w2, hv, acc[p][2]);
                    acc[p][3] = ffma2(w3, hv, acc[p][3]);
                }
            }
        }

        if (ts + 1 < T && tid < L0_NB * INP) {
            int tn = dir ? (T - 2 - ts) : (ts + 1);
            int bl = tid / INP, d = tid - bl * INP;
            x2f[nxt * L0_XBUF + (d * L0_PAIRS + (bl >> 1)) * 2 + (bl & 1)] =
                x[((size_t)(b0 + bl) * T + tn) * INP + d];
        }

        if (act) {
            float2* hw = (float2*)(h2f + nxt * L0_HBUF);
            const int col = dir * 100 + jj;
            #pragma unroll
            for (int p = 0; p < 4; p++) {
                float i0, i1, f0, f1, g0, g1, o0, o1;
                upk2(acc[p][0], i0, i1); upk2(acc[p][1], f0, f1);
                upk2(acc[p][2], g0, g1); upk2(acc[p][3], o0, o1);
                int P = grp * 4 + p;
                float c0 = c_reg[2 * p],     c1 = c_reg[2 * p + 1];
                c0 = fsig(f0) * c0 + fsig(i0) * ftanh_(g0);
                c1 = fsig(f1) * c1 + fsig(i1) * ftanh_(g1);
                float hv0 = fsig(o0) * ftanh_(c0);
                float hv1 = fsig(o1) * ftanh_(c1);
                c_reg[2 * p] = c0; c_reg[2 * p + 1] = c1;
                hw[jj * L0_PAD + P] = make_float2(hv0, hv1);
                int be = b0 + 2 * P;
                __nv_bfloat16 hb0 = __float2bfloat16(hv0);
                __nv_bfloat16 lb0 = __float2bfloat16(hv0 - __bfloat162float(hb0));
                __nv_bfloat16 hb1 = __float2bfloat16(hv1);
                __nv_bfloat16 lb1 = __float2bfloat16(hv1 - __bfloat162float(hb1));
                // [t*B + b] layout: lanes (jj) -> consecutive addresses
                size_t r0 = ((size_t)t * B + be) * KPAD + col;
                size_t r1 = r0 + KPAD;
                g_Ah[r0] = hb0; g_Al[r0] = lb0;
                g_Ah[r1] = hb1; g_Al[r1] = lb1;
                if (t == T - 1) {
                    g_h0s[(size_t)be * 200 + col]       = hv0;
                    g_h0s[(size_t)(be + 1) * 200 + col] = hv1;
                }
            }
        }
        __syncthreads();
    }
}

// ============================================================================
// Kernel 1b: split W_ih_l1f into bf16 hi/lo, [400][KPAD].
// ============================================================================
__global__ void conv_b_kernel(const float* __restrict__ wih)
{
    int i = blockIdx.x * 256 + threadIdx.x;
    if (i < 400 * 200) {
        int n = i / 200, k = i - n * 200;
        float w = wih[i];
        __nv_bfloat16 hb = __float2bfloat16(w);
        __nv_bfloat16 lb = __float2bfloat16(w - __bfloat162float(hb));
        g_Bh[n * KPAD + k] = hb;
        g_Bl[n * KPAD + k] = lb;
    }
}

// ============================================================================
// Kernel 2: xg1 GEMM via warp-level mma.sync bf16 (split hi/lo, 3 products).
// C[m][n] = sum over segs: Aseg[m][k]*Bseg[n][k].  M=131072, N=400, K=208.
// grid (1024, 5): BM=128, BN=80, BK=16; 39 = 3 seg x 13 k-chunk iterations,
// double-buffered smem (48B row stride -> conflict-free ldmatrix).
// Warp tile 32m x 40n (8 warps as 4x2); per warp/iter: 2 ldmatrix.x4 (A),
// 5 ldmatrix.x2 (B), 10 mma.m16n8k16.
// ============================================================================
__global__ void __launch_bounds__(256, 2) gemm_xg1_mma(
    const float* __restrict__ bih, const float* __restrict__ bhh)
{
    __shared__ __align__(16) __nv_bfloat16 Asm[2][128][24];
    __shared__ __align__(16) __nv_bfloat16 Bsm[2][80][24];
    __shared__ float bsm[400];

    const int tid  = threadIdx.x;
    const int wid  = tid >> 5;
    const int lane = tid & 31;
    const int m0   = blockIdx.x * 128;
    const int n0   = blockIdx.y * 80;
    const int wm   = (wid >> 1) * 32;
    const int wn   = (wid & 1) * 40;

    for (int i = tid; i < 400; i += 256) bsm[i] = bih[i] + bhh[i];

    float acc[2][5][4];
    #pragma unroll
    for (int mt = 0; mt < 2; mt++)
        #pragma unroll
        for (int nt = 0; nt < 5; nt++)
            #pragma unroll
            for (int e = 0; e < 4; e++) acc[mt][nt][e] = 0.f;

    const int arow = tid >> 1, ahalf = tid & 1;   // A: 128 rows x 2 halves
    const int brow = tid >> 1, bhalf = tid & 1;   // B: 80 rows x 2 halves (tid<160)

    // preload iteration 0 (seg 0 = Ah*Bh, k-chunk 0)
    uint4 areg = *(const uint4*)(g_Ah + (size_t)(m0 + arow) * KPAD + ahalf * 8);
    uint4 breg = make_uint4(0, 0, 0, 0);
    if (tid < 160) breg = *(const uint4*)(g_Bh + (size_t)(n0 + brow) * KPAD + bhalf * 8);
    *(uint4*)&Asm[0][arow][ahalf * 8] = areg;
    if (tid < 160) *(uint4*)&Bsm[0][brow][bhalf * 8] = breg;
    __syncthreads();

    const uint32_t a_base = smem_u32(&Asm[0][0][0]);
    const uint32_t b_base = smem_u32(&Bsm[0][0][0]);

    for (int it = 0; it < 39; it++) {
        const int cur = it & 1, nxt = cur ^ 1;
        if (it < 38) {
            const int it2 = it + 1;
            const int seg = it2 / 13, kc = it2 - seg * 13;
            const __nv_bfloat16* Ap = (seg == 1) ? g_Al : g_Ah;
            const __nv_bfloat16* Bp = (seg == 2) ? g_Bl : g_Bh;
            areg = *(const uint4*)(Ap + (size_t)(m0 + arow) * KPAD + kc * 16 + ahalf * 8);
            if (tid < 160)
                breg = *(const uint4*)(Bp + (size_t)(n0 + brow) * KPAD + kc * 16 + bhalf * 8);
        }

        const uint32_t abuf = a_base + cur * (128 * 24 * 2);
        const uint32_t bbuf = b_base + cur * (80 * 24 * 2);

        uint32_t af[2][4];
        #pragma unroll
        for (int mt = 0; mt < 2; mt++) {
            uint32_t addr = abuf + (wm + mt * 16 + (lane & 15)) * 48 + (lane >> 4) * 16;
            asm volatile("ldmatrix.sync.aligned.m8n8.x4.shared.b16 {%0,%1,%2,%3}, [%4];"
                : "=r"(af[mt][0]), "=r"(af[mt][1]), "=r"(af[mt][2]), "=r"(af[mt][3])
                : "r"(addr));
        }
        uint32_t bf[5][2];
        #pragma unroll
        for (int nt = 0; nt < 5; nt++) {
            uint32_t addr = bbuf + (wn + nt * 8 + (lane & 7)) * 48 + ((lane >> 3) & 1) * 16;
            asm volatile("ldmatrix.sync.aligned.m8n8.x2.shared.b16 {%0,%1}, [%2];"
                : "=r"(bf[nt][0]), "=r"(bf[nt][1]) : "r"(addr));
        }
        #pragma unroll
        for (int mt = 0; mt < 2; mt++)
            #pragma unroll
            for (int nt = 0; nt < 5; nt++) {
                asm volatile(
                    "mma.sync.aligned.m16n8k16.row.col.f32.bf16.bf16.f32 "
                    "{%0,%1,%2,%3}, {%4,%5,%6,%7}, {%8,%9}, {%0,%1,%2,%3};"
                    : "+f"(acc[mt][nt][0]), "+f"(acc[mt][nt][1]),
                      "+f"(acc[mt][nt][2]), "+f"(acc[mt][nt][3])
                    : "r"(af[mt][0]), "r"(af[mt][1]), "r"(af[mt][2]), "r"(af[mt][3]),
                      "r"(bf[nt][0]), "r"(bf[nt][1]));
            }

        if (it < 38) {
            *(uint4*)&Asm[nxt][arow][ahalf * 8] = areg;
            if (tid < 160) *(uint4*)&Bsm[nxt][brow][bhalf * 8] = breg;
        }
        __syncthreads();
    }

    // epilogue: c0,c1 -> (row gid, cols 2t,2t+1); c2,c3 -> row gid+8
    const int gid = lane >> 2, t4 = lane & 3;
    #pragma unroll
    for (int mt = 0; mt < 2; mt++) {
        #pragma unroll
        for (int nt = 0; nt < 5; nt++) {
            int mrow = m0 + wm + mt * 16 + gid;
            int ncol = n0 + wn + nt * 8 + t4 * 2;
            float bx = bsm[ncol - n0 + n0];        // bsm is global-indexed [0..399]
            float by = bsm[ncol + 1];
            float2 v0 = make_float2(acc[mt][nt][0] + bsm[ncol], acc[mt][nt][1] + by);
            float2 v1 = make_float2(acc[mt][nt][2] + bsm[ncol], acc[mt][nt][3] + by);
            (void)bx;
            *(float2*)&g_xg1[(size_t)mrow * 400 + ncol]       = v0;
            *(float2*)&g_xg1[(size_t)(mrow + 8) * 400 + ncol] = v1;
        }
    }
}

// ============================================================================
// Kernel 3: layer1 forward recurrence ([t*B+b] xg layout); only final h kept.
// ============================================================================
#define L1_NB   8
#define L1_PAD  5
#define L1_HBUF (100*L1_PAD*2)
#define L1_SMEMF (40000 + 2*L1_HBUF)

__global__ void __launch_bounds__(256, 1) lstm_layer1f(const float* __restrict__ whh)
{
    extern __shared__ float sm[];
    float* whh_t = sm;
    float* h2f   = sm + 40000;
    const int tid = threadIdx.x;
    const int b0 = blockIdx.x * L1_NB;

    for (int i = tid; i < 40000; i += 256) {
        int g = i / 100, k = i - g * 100;
        whh_t[k * 400 + g] = whh[i];
    }
    for (int i = tid; i < L1_HBUF; i += 256) h2f[i] = 0.f;

    const int  jj  = tid & 127;
    const int  grp = tid >> 7;
    const bool act = (jj < H);
    float c_reg[4] = {0.f, 0.f, 0.f, 0.f};

    float xr[2][4][2];
    if (act) {
        #pragma unroll
        for (int p = 0; p < 2; p++) {
            int P = grp * 2 + p;
            const float* xga = g_xg1 + ((size_t)0 * B + (b0 + 2 * P)) * 400 + jj;
            const float* xgb = xga + 400;
            #pragma unroll
            for (int g = 0; g < 4; g++) { xr[p][g][0] = xga[g * 100]; xr[p][g][1] = xgb[g * 100]; }
        }
    }

    __syncthreads();

    for (int t = 0; t < T; t++) {
        const int cur = t & 1, nxt = cur ^ 1;
        const u64* h2u = (const u64*)(h2f + cur * L1_HBUF);

        u64 acc[2][4];
        if (act) {
            #pragma unroll
            for (int p = 0; p < 2; p++)
                #pragma unroll
                for (int g = 0; g < 4; g++)
                    acc[p][g] = pk2(xr[p][g][0], xr[p][g][1]);

            if (t + 1 < T) {
                #pragma unroll
                for (int p = 0; p < 2; p++) {
                    int P = grp * 2 + p;
                    const float* xga = g_xg1 + ((size_t)(t + 1) * B + (b0 + 2 * P)) * 400 + jj;
                    const float* xgb = xga + 400;
                    #pragma unroll
                    for (int g = 0; g < 4; g++) { xr[p][g][0] = xga[g * 100]; xr[p][g][1] = xgb[g * 100]; }
                }
            }

            #pragma unroll 4
            for (int k = 0; k < H; k++) {
                const float* wr = whh_t + k * 400 + jj;
                u64 w0 = pk2(wr[0], wr[0]),     w1 = pk2(wr[100], wr[100]);
                u64 w2 = pk2(wr[200], wr[200]), w3 = pk2(wr[300], wr[300]);
                const u64* hr = h2u + k * L1_PAD + grp * 2;
                #pragma unroll
                for (int p = 0; p < 2; p++) {
                    u64 hv = hr[p];
                    acc[p][0] = ffma2(w0, hv, acc[p][0]);
                    acc[p][1] = ffma2(w1, hv, acc[p][1]);
                    acc[p][2] = ffma2(w2, hv, acc[p][2]);
                    acc[p][3] = ffma2(w3, hv, acc[p][3]);
                }
            }

            float2* hw = (float2*)(h2f + nxt * L1_HBUF);
            #pragma unroll
            for (int p = 0; p < 2; p++) {
                float i0, i1, f0, f1, g0, g1, o0, o1;
                upk2(acc[p][0], i0, i1); upk2(acc[p][1], f0, f1);
                upk2(acc[p][2], g0, g1); upk2(acc[p][3], o0, o1);
                int P = grp * 2 + p;
                float c0 = c_reg[2 * p],     c1 = c_reg[2 * p + 1];
                c0 = fsig(f0) * c0 + fsig(i0) * ftanh_(g0);
                c1 = fsig(f1) * c1 + fsig(i1) * ftanh_(g1);
                float hv0 = fsig(o0) * ftanh_(c0);
                float hv1 = fsig(o1) * ftanh_(c1);
                c_reg[2 * p] = c0; c_reg[2 * p + 1] = c1;
                hw[jj * L1_PAD + P] = make_float2(hv0, hv1);
                if (t == T - 1) {
                    int be = b0 + 2 * P;
                    g_h1f[(size_t)be * 100 + jj]       = hv0;
                    g_h1f[(size_t)(be + 1) * 100 + jj] = hv1;
                }
            }
        }
        __syncthreads();
    }
}

// ============================================================================
// Kernel 4: layer1 backward single step (c0=0 -> f-gate dead) + FC + softmax.
// grid=64, 16 batches/CTA, f32x2 packed. (unchanged from R5)
// ============================================================================
#define FN_SMEMF (30000 + 200*18 + 1600 + 300 + 600 + 4 + 48)

__global__ void __launch_bounds__(256, 1) lstm_final(
    const float* __restrict__ wih1b,
    const float* __restrict__ bih1b, const float* __restrict__ bhh1b,
    const float* __restrict__ fc_w,  const float* __restrict__ fc_b,
    float* __restrict__ out)
{
    extern __shared__ float sm[];
    float* wT   = sm;                  // [100 k][300]
    float* h0s  = sm + 30000;          // [200 k][18]
    float* h1bs = sm + 33600;          // [16][100]
    float* b3   = sm + 35200;          // [300]
    float* fcw  = sm + 35500;          // [600]
    float* fcb  = sm + 36100;          // [4]
    float* lg   = sm + 36104;          // [48]

    const int tid = threadIdx.x;
    const int b0 = blockIdx.x * 16;

    for (int i = tid; i < 16 * 200; i += 256) {
        int b = i / 200, k = i - b * 200;
        h0s[k * 18 + b] = g_h0s[(size_t)(b0 + b) * 200 + k];
    }
    for (int i = tid; i < 300; i += 256) {
        int g3 = i / 100, j = i - g3 * 100;
        int row = j + (g3 == 0 ? 0 : (g3 == 1 ? 200 : 300));
        b3[i] = bih1b[row] + bhh1b[row];
    }
    for (int i = tid; i < 600; i += 256) fcw[i] = fc_w[i];
    if (tid < 3) fcb[tid] = fc_b[tid];

    const int  jj  = tid & 127;
    const int  grp = tid >> 7;
    const bool act = (jj < H);

    u64 acc[4][3];
    #pragma unroll
    for (int p = 0; p < 4; p++)
        #pragma unroll
        for (int g = 0; g < 3; g++) acc[p][g] = pk2(0.f, 0.f);

    for (int kt = 0; kt < 2; kt++) {
        __syncthreads();
        for (int i = tid; i < 30000; i += 256) {
            int k = i % 100, j100 = i / 100;
            int grow = j100 + (j100 >= 100 ? 100 : 0);
            wT[k * 300 + j100] = wih1b[(size_t)grow * 200 + kt * 100 + k];
        }
        __syncthreads();
        if (act) {
            #pragma unroll 2
            for (int k = 0; k < 100; k++) {
                const float* wr = wT + k * 300 + jj;
                u64 w0 = pk2(wr[0], wr[0]);
                u64 w1 = pk2(wr[100], wr[100]);
                u64 w2 = pk2(wr[200], wr[200]);
                const float* hb = h0s + (kt * 100 + k) * 18 + grp * 8;
                #pragma unroll
                for (int p = 0; p < 4; p++) {
                    u64 hv = *(const u64*)(hb + 2 * p);
                    acc[p][0] = ffma2(w0, hv, acc[p][0]);
                    acc[p][1] = ffma2(w1, hv, acc[p][1]);
                    acc[p][2] = ffma2(w2, hv, acc[p][2]);
                }
            }
        }
    }
    if (act) {
        #pragma unroll
        for (int p = 0; p < 4; p++) {
            float i0, i1, g0, g1, o0, o1;
            upk2(acc[p][0], i0, i1);
            upk2(acc[p][1], g0, g1);
            upk2(acc[p][2], o0, o1);
            float bi = b3[jj], bg = b3[100 + jj], bo = b3[200 + jj];
            i0 += bi; i1 += bi; g0 += bg; g1 += bg; o0 += bo; o1 += bo;
            float c0 = fsig(i0) * ftanh_(g0);
            float c1 = fsig(i1) * ftanh_(g1);
            int bl = grp * 8 + 2 * p;
            h1bs[bl * 100 + jj]       = fsig(o0) * ftanh_(c0);
            h1bs[(bl + 1) * 100 + jj] = fsig(o1) * ftanh_(c1);
        }
    }
    __syncthreads();
    if (tid < 48) {
        int b = tid / 3, cls = tid - b * 3;
        float a = fcb[cls];
        const float* h1f = g_h1f + (size_t)(b0 + b) * 100;
        #pragma unroll 4
        for (int j = 0; j < 100; j++) {
            a += h1f[j]            * fcw[cls * 200 + j];
            a += h1bs[b * 100 + j] * fcw[cls * 200 + 100 + j];
        }
        lg[tid] = a;
    }
    __syncthreads();
    if (tid < 16) {
        int b = tid;
        float l0 = lg[b * 3], l1 = lg[b * 3 + 1], l2 = lg[b * 3 + 2];
        float m = fmaxf(l0, fmaxf(l1, l2));
        float e0 = __expf(l0 - m), e1 = __expf(l1 - m), e2 = __expf(l2 - m);
        float s = 1.0f / (e0 + e1 + e2);
        out[(b0 + b) * 3 + 0] = e0 * s;
        out[(b0 + b) * 3 + 1] = e1 * s;
        out[(b0 + b) * 3 + 2] = e2 * s;
    }
}

// ============================================================================
extern "C" void kernel_launch(void* const* d_in, const int* in_sizes, int n_in,
                              void* d_out, int out_size)
{
    (void)in_sizes; (void)n_in; (void)out_size;
    const float* x     = (const float*)d_in[0];
    const float* wih0f = (const float*)d_in[1];
    const float* whh0f = (const float*)d_in[2];
    const float* bih0f = (const float*)d_in[3];
    const float* bhh0f = (const float*)d_in[4];
    const float* wih0b = (const float*)d_in[5];
    const float* whh0b = (const float*)d_in[6];
    const float* bih0b = (const float*)d_in[7];
    const float* bhh0b = (const float*)d_in[8];
    const float* wih1f = (const float*)d_in[9];
    const float* whh1f = (const float*)d_in[10];
    const float* bih1f = (const float*)d_in[11];
    const float* bhh1f = (const float*)d_in[12];
    const float* wih1b = (const float*)d_in[13];
    const float* bih1b = (const float*)d_in[15];
    const float* bhh1b = (const float*)d_in[16];
    const float* fcw   = (const float*)d_in[17];
    const float* fcb   = (const float*)d_in[18];
    float* out = (float*)d_out;

    const int sm0 = L0_SMEMF * 4;
    const int sm1 = L1_SMEMF * 4;
    const int sm2 = FN_SMEMF * 4;
    cudaFuncSetAttribute(lstm_layer0,  cudaFuncAttributeMaxDynamicSharedMemorySize, sm0);
    cudaFuncSetAttribute(lstm_layer1f, cudaFuncAttributeMaxDynamicSharedMemorySize, sm1);
    cudaFuncSetAttribute(lstm_final,   cudaFuncAttributeMaxDynamicSharedMemorySize, sm2);

    conv_b_kernel<<<(400 * 200 + 255) / 256, 256>>>(wih1f);
    lstm_layer0<<<128, 256, sm0>>>(x, wih0f, whh0f, bih0f, bhh0f,
                                      wih0b, whh0b, bih0b, bhh0b);
    gemm_xg1_mma<<<dim3(1024, 5), 256>>>(bih1f, bhh1f);
    lstm_layer1f<<<128, 256, sm1>>>(whh1f);
    lstm_final<<<64, 256, sm2>>>(wih1b, bih1b, bhh1b, fcw, fcb, out);
}

// round 8
// speedup vs baseline: 1.1245x; 1.0477x over previous
#include <cuda_runtime.h>
#include <cuda_bf16.h>
#include <cstdint>

#define B 1024
#define T 128
#define INP 5
#define H 100
#define G4 400    // 4*H
#define MTOT (B*T)        // 131072 rows in [t*B+b] space
#define KPAD 208          // GEMM A k-stride (bf16)

// ---------------- scratch (device globals; no runtime allocation) ----------
__device__ float g_h0s[B * 2 * H];            // [b][200] h0 at t=T-1
__device__ float g_xg1[(size_t)MTOT * G4];    // [t*B+b][400] layer1-fwd gates (+bias)
__device__ float g_xg0f[(size_t)MTOT * G4];   // layer0-fwd input gates (+bias)
__device__ float g_xg0b[(size_t)MTOT * G4];   // layer0-bwd input gates (+bias)
__device__ float g_h1f[B * H];                // layer1-fwd final hidden
// bf16 split GEMM operands, [t*B+b][KPAD]; cols 200..207 stay 0 (.bss)
__device__ __nv_bfloat16 g_Ah[(size_t)MTOT * KPAD];
__device__ __nv_bfloat16 g_Al[(size_t)MTOT * KPAD];
__device__ __nv_bfloat16 g_Bh[400 * KPAD];
__device__ __nv_bfloat16 g_Bl[400 * KPAD];

typedef unsigned long long u64;

// ---------------- packed fp32x2 helpers (used by lstm_final) ----------------
__device__ __forceinline__ u64 pk2(float a, float b) {
    u64 r; asm("mov.b64 %0, {%1,%2};" : "=l"(r) : "f"(a), "f"(b)); return r;
}
__device__ __forceinline__ void upk2(u64 v, float& a, float& b) {
    asm("mov.b64 {%0,%1}, %2;" : "=f"(a), "=f"(b) : "l"(v));
}
__device__ __forceinline__ u64 ffma2(u64 a, u64 b, u64 c) {
    asm("fma.rn.f32x2 %0, %1, %2, %0;" : "+l"(c) : "l"(a), "l"(b)); return c;
}

// ---------------- fast activations ------------------------------------------
__device__ __forceinline__ float fsig(float x) {
    float e; asm("ex2.approx.f32 %0, %1;" : "=f"(e) : "f"(x * -1.4426950408889634f));
    float r; asm("rcp.approx.f32 %0, %1;" : "=f"(r) : "f"(e + 1.0f));
    return r;
}
__device__ __forceinline__ float ftanh_(float x) {
    float e; asm("ex2.approx.f32 %0, %1;" : "=f"(e) : "f"(x * -2.885390081777927f));
    float r; asm("rcp.approx.f32 %0, %1;" : "=f"(r) : "f"(e + 1.0f));
    return fmaf(2.0f, r, -1.0f);
}

__device__ __forceinline__ uint32_t smem_u32(const void* p) {
    uint32_t a;
    asm("{ .reg .u64 t; cvta.to.shared.u64 t, %1; cvt.u32.u64 %0, t; }" : "=r"(a) : "l"(p));
    return a;
}

// ============================================================================
// Kernel A: xg0 = x @ W_ih^T + (b_ih+b_hh) for one layer0 direction.
// out[(t*B+b)*400+n].  grid = MTOT/32, block 256. DRAM-write-bound.
// ============================================================================
__global__ void __launch_bounds__(256) xg0_kernel(
    const float* __restrict__ x,
    const float* __restrict__ wih, const float* __restrict__ bih,
    const float* __restrict__ bhh, float* __restrict__ out)
{
    __shared__ float ws[400 * 5];
    __shared__ float bs[400];
    __shared__ float xs[32 * 5];
    const int tid = threadIdx.x;
    const int m0 = blockIdx.x * 32;
    for (int i = tid; i < 2000; i += 256) ws[i] = wih[i];
    for (int i = tid; i < 400; i += 256) bs[i] = bih[i] + bhh[i];
    if (tid < 160) {
        int r = tid / 5, d = tid - r * 5;
        int m = m0 + r, b = m & (B - 1), t = m >> 10;
        xs[r * 5 + d] = x[((size_t)b * T + t) * INP + d];
    }
    __syncthreads();
    for (int i = tid; i < 32 * 400; i += 256) {
        int r = i / 400, n = i - r * 400;
        const float* w = ws + n * 5;
        const float* xv = xs + r * 5;
        float v = bs[n] + xv[0]*w[0] + xv[1]*w[1] + xv[2]*w[2] + xv[3]*w[3] + xv[4]*w[4];
        out[(size_t)(m0 + r) * 400 + n] = v;
    }
}

// ============================================================================
// Kernel B (UNIFIED TENSOR-CORE RECURRENCE): 16 batches/CTA, 256 thr, 8 warps.
// Per step: gates[16][400] = h[16][100] @ Whh^T via mma.sync bf16 split
// (Ah*Wh + Al*Wh + Ah*Wl), acc init from precomputed xg; then activations.
// mode 0: layer0 (grid 128: dir=bid>>6), emits g_Ah/g_Al bf16 + g_h0s@T-1.
// mode 1: layer1 fwd (grid 64), emits g_h1f@T-1.
// SMEM: Wh[400][120]bf16 | Wl | Ah_st[16][120] | Al_st | gates[16][404]f32
// ============================================================================
#define KSB     240                     // 120 bf16 k-stride, bank-conflict-free
#define OFF_WL  96000
#define OFF_AH  192000
#define OFF_AL  195840
#define OFF_GT  199680
#define GSTR    404
#define RC_SMEM (199680 + 16*GSTR*4)    // 225,536 B

__global__ void __launch_bounds__(256, 1) lstm_rec_mma(
    const float* __restrict__ xgf, const float* __restrict__ xgb,
    const float* __restrict__ whf, const float* __restrict__ whb,
    int mode)
{
    extern __shared__ char smc[];
    const uint32_t sb = smem_u32(smc);
    const int tid = threadIdx.x, wid = tid >> 5, lane = tid & 31;
    const int dir = (mode == 0) ? (int)(blockIdx.x >> 6) : 0;
    const int b0  = (mode == 0) ? (int)(blockIdx.x & 63) * 16 : (int)blockIdx.x * 16;
    const float* xgp = dir ? xgb : xgf;
    const float* wp  = dir ? whb : whf;

    // zero W + A-staging region (pads must be 0), then fill W splits
    for (int i = tid; i < (OFF_GT >> 4); i += 256)
        ((uint4*)smc)[i] = make_uint4(0, 0, 0, 0);
    __syncthreads();
    for (int i = tid; i < 400 * 100; i += 256) {
        int n = i / 100, k = i - n * 100;
        float w = wp[i];
        __nv_bfloat16 hb = __float2bfloat16(w);
        __nv_bfloat16 lb = __float2bfloat16(w - __bfloat162float(hb));
        *(__nv_bfloat16*)(smc + n * KSB + k * 2) = hb;
        *(__nv_bfloat16*)(smc + OFF_WL + n * KSB + k * 2) = lb;
    }
    __syncthreads();

    const int g  = lane >> 2;     // mma row 0..7
    const int t4 = lane & 3;      // mma col group
    const int ab = tid >> 4;      // activation batch 0..15
    const int jb = tid & 15;      // activation j base

    float cst[7];
    #pragma unroll
    for (int i = 0; i < 7; i++) cst[i] = 0.f;

    float xp[7][4];
    {   // prefetch first step's xg
        int tg = dir ? (T - 1) : 0;
        #pragma unroll
        for (int nt = 0; nt < 7; nt++) {
            int tile = wid * 7 + nt;
            if (tile < 50) {
                const float* p0 = xgp + ((size_t)tg * B + b0 + g) * 400 + tile * 8 + 2 * t4;
                float2 v0 = *(const float2*)p0;
                float2 v1 = *(const float2*)(p0 + 3200);
                xp[nt][0] = v0.x; xp[nt][1] = v0.y; xp[nt][2] = v1.x; xp[nt][3] = v1.y;
            } else { xp[nt][0] = xp[nt][1] = xp[nt][2] = xp[nt][3] = 0.f; }
        }
    }

    for (int ts = 0; ts < T; ts++) {
        const int tg = dir ? (T - 1 - ts) : ts;

        float acc[7][4];
        #pragma unroll
        for (int nt = 0; nt < 7; nt++) {
            acc[nt][0] = xp[nt][0]; acc[nt][1] = xp[nt][1];
            acc[nt][2] = xp[nt][2]; acc[nt][3] = xp[nt][3];
        }
        if (ts + 1 < T) {   // prefetch next step's xg; lands under the MMAs
            int tn = dir ? (tg - 1) : (tg + 1);
            #pragma unroll
            for (int nt = 0; nt < 7; nt++) {
                int tile = wid * 7 + nt;
                if (tile < 50) {
                    const float* p0 = xgp + ((size_t)tn * B + b0 + g) * 400 + tile * 8 + 2 * t4;
                    float2 v0 = *(const float2*)p0;
                    float2 v1 = *(const float2*)(p0 + 3200);
                    xp[nt][0] = v0.x; xp[nt][1] = v0.y; xp[nt][2] = v1.x; xp[nt][3] = v1.y;
                }
            }
        }

        // ---- MMA phase: 7 k-chunks x 7 n-tiles x 3 split products ----
        #pragma unroll
        for (int kc = 0; kc < 7; kc++) {
            uint32_t ah[4], al[4];
            uint32_t aaddr = sb + OFF_AH + (lane & 15) * KSB + (lane >> 4) * 16 + kc * 32;
            asm volatile("ldmatrix.sync.aligned.m8n8.x4.shared.b16 {%0,%1,%2,%3}, [%4];"
                : "=r"(ah[0]), "=r"(ah[1]), "=r"(ah[2]), "=r"(ah[3]) : "r"(aaddr));
            asm volatile("ldmatrix.sync.aligned.m8n8.x4.shared.b16 {%0,%1,%2,%3}, [%4];"
                : "=r"(al[0]), "=r"(al[1]), "=r"(al[2]), "=r"(al[3]) : "r"(aaddr + 3840));
            #pragma unroll
            for (int nt = 0; nt < 7; nt++) {
                uint32_t waddr = sb + ((wid * 7 + nt) * 8 + (lane & 7)) * KSB
                               + ((lane >> 3) & 1) * 16 + kc * 32;
                uint32_t wh[2], wl[2];
                asm volatile("ldmatrix.sync.aligned.m8n8.x2.shared.b16 {%0,%1}, [%2];"
                    : "=r"(wh[0]), "=r"(wh[1]) : "r"(waddr));
                asm volatile("ldmatrix.sync.aligned.m8n8.x2.shared.b16 {%0,%1}, [%2];"
                    : "=r"(wl[0]), "=r"(wl[1]) : "r"(waddr + OFF_WL));
                asm volatile(
                    "mma.sync.aligned.m16n8k16.row.col.f32.bf16.bf16.f32 "
                    "{%0,%1,%2,%3}, {%4,%5,%6,%7}, {%8,%9}, {%0,%1,%2,%3};"
                    : "+f"(acc[nt][0]), "+f"(acc[nt][1]), "+f"(acc[nt][2]), "+f"(acc[nt][3])
                    : "r"(ah[0]), "r"(ah[1]), "r"(ah[2]), "r"(ah[3]), "r"(wh[0]), "r"(wh[1]));
                asm volatile(
                    "mma.sync.aligned.m16n8k16.row.col.f32.bf16.bf16.f32 "
                    "{%0,%1,%2,%3}, {%4,%5,%6,%7}, {%8,%9}, {%0,%1,%2,%3};"
                    : "+f"(acc[nt][0]), "+f"(acc[nt][1]), "+f"(acc[nt][2]), "+f"(acc[nt][3])
                    : "r"(al[0]), "r"(al[1]), "r"(al[2]), "r"(al[3]), "r"(wh[0]), "r"(wh[1]));
                asm volatile(
                    "mma.sync.aligned.m16n8k16.row.col.f32.bf16.bf16.f32 "
                    "{%0,%1,%2,%3}, {%4,%5,%6,%7}, {%8,%9}, {%0,%1,%2,%3};"
                    : "+f"(acc[nt][0]), "+f"(acc[nt][1]), "+f"(acc[nt][2]), "+f"(acc[nt][3])
                    : "r"(ah[0]), "r"(ah[1]), "r"(ah[2]), "r"(ah[3]), "r"(wl[0]), "r"(wl[1]));
            }
        }

        // ---- C-frags -> gates smem ----
        #pragma unroll
        for (int nt = 0; nt < 7; nt++) {
            int tile = wid * 7 + nt;
            if (tile < 50) {
                uint32_t gaddr = sb + OFF_GT + (g * GSTR + tile * 8 + 2 * t4) * 4;
                asm volatile("st.shared.v2.f32 [%0], {%1,%2};"
                    :: "r"(gaddr), "f"(acc[nt][0]), "f"(acc[nt][1]) : "memory");
                asm volatile("st.shared.v2.f32 [%0], {%1,%2};"
                    :: "r"(gaddr + 8 * GSTR * 4), "f"(acc[nt][2]), "f"(acc[nt][3]) : "memory");
            }
        }
        __syncthreads();

        // ---- activations; repack h into A-staging (hi/lo bf16) ----
        const float* gbase = (const float*)(smc + OFF_GT) + ab * GSTR;
        #pragma unroll
        for (int jo = 0; jo < 7; jo++) {
            int j = jb + jo * 16;
            if (j < 100) {
                float gi = gbase[j], gf = gbase[100 + j];
                float gg = gbase[200 + j], go = gbase[300 + j];
                float cv = fsig(gf) * cst[jo] + fsig(gi) * ftanh_(gg);
                cst[jo] = cv;
                float h = fsig(go) * ftanh_(cv);
                __nv_bfloat16 hh = __float2bfloat16(h);
                __nv_bfloat16 hl = __float2bfloat16(h - __bfloat162float(hh));
                *(__nv_bfloat16*)(smc + OFF_AH + ab * KSB + j * 2) = hh;
                *(__nv_bfloat16*)(smc + OFF_AL + ab * KSB + j * 2) = hl;
                if (mode == 0) {
                    size_t r = ((size_t)tg * B + b0 + ab) * KPAD + dir * 100 + j;
                    g_Ah[r] = hh; g_Al[r] = hl;
                    if (tg == T - 1)
                        g_h0s[(size_t)(b0 + ab) * 200 + dir * 100 + j] = h;
                } else if (ts == T - 1) {
                    g_h1f[(size_t)(b0 + ab) * 100 + j] = h;
                }
            }
        }
        __syncthreads();
    }
}

// ============================================================================
// Kernel 1b: split W_ih_l1f into bf16 hi/lo, [400][KPAD].
// ============================================================================
__global__ void conv_b_kernel(const float* __restrict__ wih)
{
    int i = blockIdx.x * 256 + threadIdx.x;
    if (i < 400 * 200) {
        int n = i / 200, k = i - n * 200;
        float w = wih[i];
        __nv_bfloat16 hb = __float2bfloat16(w);
        __nv_bfloat16 lb = __float2bfloat16(w - __bfloat162float(hb));
        g_Bh[n * KPAD + k] = hb;
        g_Bl[n * KPAD + k] = lb;
    }
}

// ============================================================================
// Kernel 2: xg1 GEMM via mma.sync bf16 (split hi/lo, 3 products). (R7, working)
// ============================================================================
__global__ void __launch_bounds__(256, 2) gemm_xg1_mma(
    const float* __restrict__ bih, const float* __restrict__ bhh)
{
    __shared__ __align__(16) __nv_bfloat16 Asm[2][128][24];
    __shared__ __align__(16) __nv_bfloat16 Bsm[2][80][24];
    __shared__ float bsm[400];

    const int tid  = threadIdx.x;
    const int wid  = tid >> 5;
    const int lane = tid & 31;
    const int m0   = blockIdx.x * 128;
    const int n0   = blockIdx.y * 80;
    const int wm   = (wid >> 1) * 32;
    const int wn   = (wid & 1) * 40;

    for (int i = tid; i < 400; i += 256) bsm[i] = bih[i] + bhh[i];

    float acc[2][5][4];
    #pragma unroll
    for (int mt = 0; mt < 2; mt++)
        #pragma unroll
        for (int nt = 0; nt < 5; nt++)
            #pragma unroll
            for (int e = 0; e < 4; e++) acc[mt][nt][e] = 0.f;

    const int arow = tid >> 1, ahalf = tid & 1;
    const int brow = tid >> 1, bhalf = tid & 1;

    uint4 areg = *(const uint4*)(g_Ah + (size_t)(m0 + arow) * KPAD + ahalf * 8);
    uint4 breg = make_uint4(0, 0, 0, 0);
    if (tid < 160) breg = *(const uint4*)(g_Bh + (size_t)(n0 + brow) * KPAD + bhalf * 8);
    *(uint4*)&Asm[0][arow][ahalf * 8] = areg;
    if (tid < 160) *(uint4*)&Bsm[0][brow][bhalf * 8] = breg;
    __syncthreads();

    const uint32_t a_base = smem_u32(&Asm[0][0][0]);
    const uint32_t b_base = smem_u32(&Bsm[0][0][0]);

    for (int it = 0; it < 39; it++) {
        const int cur = it & 1, nxt = cur ^ 1;
        if (it < 38) {
            const int it2 = it + 1;
            const int seg = it2 / 13, kc = it2 - seg * 13;
            const __nv_bfloat16* Ap = (seg == 1) ? g_Al : g_Ah;
            const __nv_bfloat16* Bp = (seg == 2) ? g_Bl : g_Bh;
            areg = *(const uint4*)(Ap + (size_t)(m0 + arow) * KPAD + kc * 16 + ahalf * 8);
            if (tid < 160)
                breg = *(const uint4*)(Bp + (size_t)(n0 + brow) * KPAD + kc * 16 + bhalf * 8);
        }
        const uint32_t abuf = a_base + cur * (128 * 24 * 2);
        const uint32_t bbuf = b_base + cur * (80 * 24 * 2);

        uint32_t af[2][4];
        #pragma unroll
        for (int mt = 0; mt < 2; mt++) {
            uint32_t addr = abuf + (wm + mt * 16 + (lane & 15)) * 48 + (lane >> 4) * 16;
            asm volatile("ldmatrix.sync.aligned.m8n8.x4.shared.b16 {%0,%1,%2,%3}, [%4];"
                : "=r"(af[mt][0]), "=r"(af[mt][1]), "=r"(af[mt][2]), "=r"(af[mt][3])
                : "r"(addr));
        }
        uint32_t bf[5][2];
        #pragma unroll
        for (int nt = 0; nt < 5; nt++) {
            uint32_t addr = bbuf + (wn + nt * 8 + (lane & 7)) * 48 + ((lane >> 3) & 1) * 16;
            asm volatile("ldmatrix.sync.aligned.m8n8.x2.shared.b16 {%0,%1}, [%2];"
                : "=r"(bf[nt][0]), "=r"(bf[nt][1]) : "r"(addr));
        }
        #pragma unroll
        for (int mt = 0; mt < 2; mt++)
            #pragma unroll
            for (int nt = 0; nt < 5; nt++) {
                asm volatile(
                    "mma.sync.aligned.m16n8k16.row.col.f32.bf16.bf16.f32 "
                    "{%0,%1,%2,%3}, {%4,%5,%6,%7}, {%8,%9}, {%0,%1,%2,%3};"
                    : "+f"(acc[mt][nt][0]), "+f"(acc[mt][nt][1]),
                      "+f"(acc[mt][nt][2]), "+f"(acc[mt][nt][3])
                    : "r"(af[mt][0]), "r"(af[mt][1]), "r"(af[mt][2]), "r"(af[mt][3]),
                      "r"(bf[nt][0]), "r"(bf[nt][1]));
            }
        if (it < 38) {
            *(uint4*)&Asm[nxt][arow][ahalf * 8] = areg;
            if (tid < 160) *(uint4*)&Bsm[nxt][brow][bhalf * 8] = breg;
        }
        __syncthreads();
    }

    const int gid = lane >> 2, t4 = lane & 3;
    #pragma unroll
    for (int mt = 0; mt < 2; mt++) {
        #pragma unroll
        for (int nt = 0; nt < 5; nt++) {
            int mrow = m0 + wm + mt * 16 + gid;
            int ncol = n0 + wn + nt * 8 + t4 * 2;
            float by = bsm[ncol + 1];
            float2 v0 = make_float2(acc[mt][nt][0] + bsm[ncol], acc[mt][nt][1] + by);
            float2 v1 = make_float2(acc[mt][nt][2] + bsm[ncol], acc[mt][nt][3] + by);
            *(float2*)&g_xg1[(size_t)mrow * 400 + ncol]       = v0;
            *(float2*)&g_xg1[(size_t)(mrow + 8) * 400 + ncol] = v1;
        }
    }
}

// ============================================================================
// Kernel 4: layer1 backward single step (c0=0 -> f-gate dead) + FC + softmax.
// grid=64, 16 batches/CTA. (R5/R7, working)
// ============================================================================
#define FN_SMEMF (30000 + 200*18 + 1600 + 300 + 600 + 4 + 48)

__global__ void __launch_bounds__(256, 1) lstm_final(
    const float* __restrict__ wih1b,
    const float* __restrict__ bih1b, const float* __restrict__ bhh1b,
    const float* __restrict__ fc_w,  const float* __restrict__ fc_b,
    float* __restrict__ out)
{
    extern __shared__ float sm[];
    float* wT   = sm;
    float* h0s  = sm + 30000;
    float* h1bs = sm + 33600;
    float* b3   = sm + 35200;
    float* fcw  = sm + 35500;
    float* fcb  = sm + 36100;
    float* lg   = sm + 36104;

    const int tid = threadIdx.x;
    const int b0 = blockIdx.x * 16;

    for (int i = tid; i < 16 * 200; i += 256) {
        int b = i / 200, k = i - b * 200;
        h0s[k * 18 + b] = g_h0s[(size_t)(b0 + b) * 200 + k];
    }
    for (int i = tid; i < 300; i += 256) {
        int g3 = i / 100, j = i - g3 * 100;
        int row = j + (g3 == 0 ? 0 : (g3 == 1 ? 200 : 300));
        b3[i] = bih1b[row] + bhh1b[row];
    }
    for (int i = tid; i < 600; i += 256) fcw[i] = fc_w[i];
    if (tid < 3) fcb[tid] = fc_b[tid];

    const int  jj  = tid & 127;
    const int  grp = tid >> 7;
    const bool act = (jj < H);

    u64 acc[4][3];
    #pragma unroll
    for (int p = 0; p < 4; p++)
        #pragma unroll
        for (int g = 0; g < 3; g++) acc[p][g] = pk2(0.f, 0.f);

    for (int kt = 0; kt < 2; kt++) {
        __syncthreads();
        for (int i = tid; i < 30000; i += 256) {
            int k = i % 100, j100 = i / 100;
            int grow = j100 + (j100 >= 100 ? 100 : 0);
            wT[k * 300 + j100] = wih1b[(size_t)grow * 200 + kt * 100 + k];
        }
        __syncthreads();
        if (act) {
            #pragma unroll 2
            for (int k = 0; k < 100; k++) {
                const float* wr = wT + k * 300 + jj;
                u64 w0 = pk2(wr[0], wr[0]);
                u64 w1 = pk2(wr[100], wr[100]);
                u64 w2 = pk2(wr[200], wr[200]);
                const float* hb = h0s + (kt * 100 + k) * 18 + grp * 8;
                #pragma unroll
                for (int p = 0; p < 4; p++) {
                    u64 hv = *(const u64*)(hb + 2 * p);
                    acc[p][0] = ffma2(w0, hv, acc[p][0]);
                    acc[p][1] = ffma2(w1, hv, acc[p][1]);
                    acc[p][2] = ffma2(w2, hv, acc[p][2]);
                }
            }
        }
    }
    if (act) {
        #pragma unroll
        for (int p = 0; p < 4; p++) {
            float i0, i1, g0, g1, o0, o1;
            upk2(acc[p][0], i0, i1);
            upk2(acc[p][1], g0, g1);
            upk2(acc[p][2], o0, o1);
            float bi = b3[jj], bg = b3[100 + jj], bo = b3[200 + jj];
            i0 += bi; i1 += bi; g0 += bg; g1 += bg; o0 += bo; o1 += bo;
            float c0 = fsig(i0) * ftanh_(g0);
            float c1 = fsig(i1) * ftanh_(g1);
            int bl = grp * 8 + 2 * p;
            h1bs[bl * 100 + jj]       = fsig(o0) * ftanh_(c0);
            h1bs[(bl + 1) * 100 + jj] = fsig(o1) * ftanh_(c1);
        }
    }
    __syncthreads();
    if (tid < 48) {
        int b = tid / 3, cls = tid - b * 3;
        float a = fcb[cls];
        const float* h1f = g_h1f + (size_t)(b0 + b) * 100;
        #pragma unroll 4
        for (int j = 0; j < 100; j++) {
            a += h1f[j]            * fcw[cls * 200 + j];
            a += h1bs[b * 100 + j] * fcw[cls * 200 + 100 + j];
        }
        lg[tid] = a;
    }
    __syncthreads();
    if (tid < 16) {
        int b = tid;
        float l0 = lg[b * 3], l1 = lg[b * 3 + 1], l2 = lg[b * 3 + 2];
        float m = fmaxf(l0, fmaxf(l1, l2));
        float e0 = __expf(l0 - m), e1 = __expf(l1 - m), e2 = __expf(l2 - m);
        float s = 1.0f / (e0 + e1 + e2);
        out[(b0 + b) * 3 + 0] = e0 * s;
        out[(b0 + b) * 3 + 1] = e1 * s;
        out[(b0 + b) * 3 + 2] = e2 * s;
    }
}

// ============================================================================
extern "C" void kernel_launch(void* const* d_in, const int* in_sizes, int n_in,
                              void* d_out, int out_size)
{
    (void)in_sizes; (void)n_in; (void)out_size;
    const float* x     = (const float*)d_in[0];
    const float* wih0f = (const float*)d_in[1];
    const float* whh0f = (const float*)d_in[2];
    const float* bih0f = (const float*)d_in[3];
    const float* bhh0f = (const float*)d_in[4];
    const float* wih0b = (const float*)d_in[5];
    const float* whh0b = (const float*)d_in[6];
    const float* bih0b = (const float*)d_in[7];
    const float* bhh0b = (const float*)d_in[8];
    const float* wih1f = (const float*)d_in[9];
    const float* whh1f = (const float*)d_in[10];
    const float* bih1f = (const float*)d_in[11];
    const float* bhh1f = (const float*)d_in[12];
    const float* wih1b = (const float*)d_in[13];
    const float* bih1b = (const float*)d_in[15];
    const float* bhh1b = (const float*)d_in[16];
    const float* fcw   = (const float*)d_in[17];
    const float* fcb   = (const float*)d_in[18];
    float* out = (float*)d_out;

    float* xg0f; cudaGetSymbolAddress((void**)&xg0f, g_xg0f);
    float* xg0b; cudaGetSymbolAddress((void**)&xg0b, g_xg0b);
    float* xg1p; cudaGetSymbolAddress((void**)&xg1p, g_xg1);

    cudaFuncSetAttribute(lstm_rec_mma, cudaFuncAttributeMaxDynamicSharedMemorySize, RC_SMEM);
    cudaFuncSetAttribute(lstm_final,   cudaFuncAttributeMaxDynamicSharedMemorySize, FN_SMEMF * 4);

    conv_b_kernel<<<(400 * 200 + 255) / 256, 256>>>(wih1f);
    xg0_kernel<<<MTOT / 32, 256>>>(x, wih0f, bih0f, bhh0f, xg0f);
    xg0_kernel<<<MTOT / 32, 256>>>(x, wih0b, bih0b, bhh0b, xg0b);
    lstm_rec_mma<<<128, 256, RC_SMEM>>>(xg0f, xg0b, whh0f, whh0b, 0);
    gemm_xg1_mma<<<dim3(1024, 5), 256>>>(bih1f, bhh1f);
    lstm_rec_mma<<<64, 256, RC_SMEM>>>(xg1p, xg1p, whh1f, whh1f, 1);
    lstm_final<<<64, 256, FN_SMEMF * 4>>>(wih1b, bih1b, bhh1b, fcw, fcb, out);
}

// round 9
// speedup vs baseline: 1.2440x; 1.1063x over previous
#include <cuda_runtime.h>
#include <cuda_bf16.h>
#include <cstdint>

#define B 1024
#define T 128
#define INP 5
#define H 100
#define G4 400
#define MTOT (B*T)
#define KPAD 208

// ---------------- scratch (device globals; no runtime allocation) ----------
__device__ float g_h0s[B * 2 * H];            // [b][200] h0 at t=T-1
__device__ float g_xg1[(size_t)MTOT * G4];    // [t*B+b][n'] layer1-fwd gates (+bias), gate-interleaved
__device__ float g_h1f[B * H];
__device__ __nv_bfloat16 g_Ah[(size_t)MTOT * KPAD];   // h0 hi, [t*B+b][k]; cols 200..207 = 0
__device__ __nv_bfloat16 g_Al[(size_t)MTOT * KPAD];
__device__ __nv_bfloat16 g_Bh[400 * KPAD];            // W_ih_l1f rows gate-interleaved
__device__ __nv_bfloat16 g_Bl[400 * KPAD];

typedef unsigned long long u64;

__device__ __forceinline__ u64 pk2(float a, float b) {
    u64 r; asm("mov.b64 %0, {%1,%2};" : "=l"(r) : "f"(a), "f"(b)); return r;
}
__device__ __forceinline__ void upk2(u64 v, float& a, float& b) {
    asm("mov.b64 {%0,%1}, %2;" : "=f"(a), "=f"(b) : "l"(v));
}
__device__ __forceinline__ u64 ffma2(u64 a, u64 b, u64 c) {
    asm("fma.rn.f32x2 %0, %1, %2, %0;" : "+l"(c) : "l"(a), "l"(b)); return c;
}
__device__ __forceinline__ float fsig(float x) {
    float e; asm("ex2.approx.f32 %0, %1;" : "=f"(e) : "f"(x * -1.4426950408889634f));
    float r; asm("rcp.approx.f32 %0, %1;" : "=f"(r) : "f"(e + 1.0f));
    return r;
}
__device__ __forceinline__ float ftanh_(float x) {
    float e; asm("ex2.approx.f32 %0, %1;" : "=f"(e) : "f"(x * -2.885390081777927f));
    float r; asm("rcp.approx.f32 %0, %1;" : "=f"(r) : "f"(e + 1.0f));
    return fmaf(2.0f, r, -1.0f);
}
__device__ __forceinline__ uint32_t smem_u32(const void* p) {
    uint32_t a;
    asm("{ .reg .u64 t; cvta.to.shared.u64 t, %1; cvt.u32.u64 %0, t; }" : "=r"(a) : "l"(p));
    return a;
}

#define MMA_BF16(ac, a0,a1,a2,a3, b0,b1) \
    asm volatile("mma.sync.aligned.m16n8k16.row.col.f32.bf16.bf16.f32 " \
        "{%0,%1,%2,%3}, {%4,%5,%6,%7}, {%8,%9}, {%0,%1,%2,%3};" \
        : "+f"((ac)[0]), "+f"((ac)[1]), "+f"((ac)[2]), "+f"((ac)[3]) \
        : "r"(a0), "r"(a1), "r"(a2), "r"(a3), "r"(b0), "r"(b1))

// ============================================================================
// UNIFIED TENSOR-CORE RECURRENCE, gate-interleaved (n' = j*4 + gate).
// 16 batches/CTA, 256 thr. Per step ONE barrier: MMA (x-proj folded into
// k=100..104) -> shfl.bfly gate exchange -> in-register activations -> h
// written to double-buffered A staging.
// mode 0: layer0 (grid 128), emits g_Ah/g_Al + g_h0s. mode 1: layer1 fwd
// (grid 64), acc init from g_xg1, emits g_h1f.
// SMEM: Wh[400][120] | Wl | A bufs x2 (Ah[16][120] + Al)
// ============================================================================
#define KSB     240
#define OFF_WL  96000
#define OFF_A   192000
#define ABUF    7680
#define RC_SMEM 207360

__global__ void __launch_bounds__(256, 1) lstm_rec_mma(
    const float* __restrict__ xg,
    const float* __restrict__ x,
    const float* __restrict__ whf, const float* __restrict__ whb,
    const float* __restrict__ wihf, const float* __restrict__ wihb,
    const float* __restrict__ bihf, const float* __restrict__ bhhf,
    const float* __restrict__ bihb, const float* __restrict__ bhhb,
    int mode)
{
    extern __shared__ char smc[];
    const uint32_t sb = smem_u32(smc);
    const int tid = threadIdx.x, wid = tid >> 5, lane = tid & 31;
    const int g = lane >> 2, t4 = lane & 3;
    const int dir = (mode == 0) ? (int)(blockIdx.x >> 6) : 0;
    const int b0  = (mode == 0) ? (int)(blockIdx.x & 63) * 16 : (int)blockIdx.x * 16;
    const float* wp  = dir ? whb  : whf;
    const float* wip = dir ? wihb : wihf;
    const float* bi_ = dir ? bihb : bihf;
    const float* bh_ = dir ? bhhb : bhhf;

    // zero everything (W pads, A pads, h=0 initial state)
    for (int i = tid; i < (RC_SMEM >> 4); i += 256)
        ((uint4*)smc)[i] = make_uint4(0, 0, 0, 0);
    __syncthreads();
    // W fill: row n' = j*4+gate <- orig row gate*100+j ; k 0..99 = Whh
    for (int i = tid; i < 400 * 100; i += 256) {
        int r = i / 100, k = i - r * 100;
        int np = (r % 100) * 4 + r / 100;
        float w = wp[i];
        __nv_bfloat16 hb = __float2bfloat16(w);
        __nv_bfloat16 lb = __float2bfloat16(w - __bfloat162float(hb));
        *(__nv_bfloat16*)(smc + np * KSB + k * 2) = hb;
        *(__nv_bfloat16*)(smc + OFF_WL + np * KSB + k * 2) = lb;
    }
    if (mode == 0) {
        // W_ih into k cols 100..104
        for (int i = tid; i < 400 * INP; i += 256) {
            int r = i / INP, d = i - r * INP;
            int np = (r % 100) * 4 + r / 100;
            float w = wip[i];
            __nv_bfloat16 hb = __float2bfloat16(w);
            __nv_bfloat16 lb = __float2bfloat16(w - __bfloat162float(hb));
            *(__nv_bfloat16*)(smc + np * KSB + (100 + d) * 2) = hb;
            *(__nv_bfloat16*)(smc + OFF_WL + np * KSB + (100 + d) * 2) = lb;
        }
        // x for first step into buf0 cols 100..104
        if (tid < 16 * INP) {
            int bb = tid / INP, d = tid - (tid / INP) * INP;
            int tg0 = dir ? (T - 1) : 0;
            float xv = x[((size_t)(b0 + bb) * T + tg0) * INP + d];
            __nv_bfloat16 hb = __float2bfloat16(xv);
            __nv_bfloat16 lb = __float2bfloat16(xv - __bfloat162float(hb));
            *(__nv_bfloat16*)(smc + OFF_A + bb * KSB + (100 + d) * 2) = hb;
            *(__nv_bfloat16*)(smc + OFF_A + 3840 + bb * KSB + (100 + d) * 2) = lb;
        }
    }

    // warp tile slots: round-robin, dummies clamped to tile 0 (results discarded)
    int  tl[7]; bool tv[7];
    float br[7][2];
    #pragma unroll
    for (int i = 0; i < 7; i++) {
        int t = wid + 8 * i;
        tv[i] = (t < 50); tl[i] = tv[i] ? t : 0;
        br[i][0] = br[i][1] = 0.f;
        if (mode == 0 && tv[i]) {
            int np = t * 8 + 2 * t4;
            int r0 = (np & 3) * 100 + (np >> 2);
            int r1 = ((np + 1) & 3) * 100 + ((np + 1) >> 2);
            br[i][0] = bi_[r0] + bh_[r0];
            br[i][1] = bi_[r1] + bh_[r1];
        }
    }
    float cst[7];
    #pragma unroll
    for (int i = 0; i < 7; i++) cst[i] = 0.f;

    float xp[7][4];
    if (mode == 1) {
        #pragma unroll
        for (int i = 0; i < 7; i++) {
            xp[i][0] = xp[i][1] = xp[i][2] = xp[i][3] = 0.f;
            if (tv[i]) {
                const float* p0 = xg + (size_t)(b0 + g) * 400 + tl[i] * 8 + 2 * t4;
                float2 v0 = *(const float2*)p0;
                float2 v1 = *(const float2*)(p0 + 3200);
                xp[i][0] = v0.x; xp[i][1] = v0.y; xp[i][2] = v1.x; xp[i][3] = v1.y;
            }
        }
    }
    __syncthreads();

    for (int ts = 0; ts < T; ts++) {
        const int cur = ts & 1, nxt = cur ^ 1;
        const int tg = dir ? (T - 1 - ts) : ts;

        float acc[7][4];
        if (mode == 0) {
            #pragma unroll
            for (int i = 0; i < 7; i++) {
                acc[i][0] = br[i][0]; acc[i][1] = br[i][1];
                acc[i][2] = br[i][0]; acc[i][3] = br[i][1];
            }
        } else {
            #pragma unroll
            for (int i = 0; i < 7; i++) {
                acc[i][0] = xp[i][0]; acc[i][1] = xp[i][1];
                acc[i][2] = xp[i][2]; acc[i][3] = xp[i][3];
            }
            if (ts + 1 < T) {
                #pragma unroll
                for (int i = 0; i < 7; i++) {
                    if (tv[i]) {
                        const float* p0 = xg + ((size_t)(ts + 1) * B + b0 + g) * 400 + tl[i] * 8 + 2 * t4;
                        float2 v0 = *(const float2*)p0;
                        float2 v1 = *(const float2*)(p0 + 3200);
                        xp[i][0] = v0.x; xp[i][1] = v0.y; xp[i][2] = v1.x; xp[i][3] = v1.y;
                    }
                }
            }
        }
        // prefetch next step's x (mode 0)
        float xv = 0.f;
        if (mode == 0 && tid < 16 * INP && ts + 1 < T) {
            int bb = tid / INP, d = tid - (tid / INP) * INP;
            int tgn = dir ? (tg - 1) : (tg + 1);
            xv = x[((size_t)(b0 + bb) * T + tgn) * INP + d];
        }

        // ---- MMA: 7 k-chunks x 7 slots x 3 split products ----
        const uint32_t aBase = sb + OFF_A + cur * ABUF;
        #pragma unroll
        for (int kc = 0; kc < 7; kc++) {
            uint32_t ah[4], al[4];
            uint32_t aa = aBase + (lane & 15) * KSB + (lane >> 4) * 16 + kc * 32;
            asm volatile("ldmatrix.sync.aligned.m8n8.x4.shared.b16 {%0,%1,%2,%3}, [%4];"
                : "=r"(ah[0]), "=r"(ah[1]), "=r"(ah[2]), "=r"(ah[3]) : "r"(aa));
            asm volatile("ldmatrix.sync.aligned.m8n8.x4.shared.b16 {%0,%1,%2,%3}, [%4];"
                : "=r"(al[0]), "=r"(al[1]), "=r"(al[2]), "=r"(al[3]) : "r"(aa + 3840));

            uint32_t wh[7][2], wl[7][2];
            #pragma unroll
            for (int p = 0; p < 3; p++) {
                int m = lane >> 3;
                int tt = tl[2 * p + (m >> 1)];
                uint32_t wa = sb + (8 * tt + (lane & 7)) * KSB + (m & 1) * 16 + kc * 32;
                asm volatile("ldmatrix.sync.aligned.m8n8.x4.shared.b16 {%0,%1,%2,%3}, [%4];"
                    : "=r"(wh[2*p][0]), "=r"(wh[2*p][1]), "=r"(wh[2*p+1][0]), "=r"(wh[2*p+1][1])
                    : "r"(wa));
                asm volatile("ldmatrix.sync.aligned.m8n8.x4.shared.b16 {%0,%1,%2,%3}, [%4];"
                    : "=r"(wl[2*p][0]), "=r"(wl[2*p][1]), "=r"(wl[2*p+1][0]), "=r"(wl[2*p+1][1])
                    : "r"(wa + OFF_WL));
            }
            {
                uint32_t wa = sb + (8 * tl[6] + (lane & 7)) * KSB + ((lane >> 3) & 1) * 16 + kc * 32;
                asm volatile("ldmatrix.sync.aligned.m8n8.x2.shared.b16 {%0,%1}, [%2];"
                    : "=r"(wh[6][0]), "=r"(wh[6][1]) : "r"(wa));
                asm volatile("ldmatrix.sync.aligned.m8n8.x2.shared.b16 {%0,%1}, [%2];"
                    : "=r"(wl[6][0]), "=r"(wl[6][1]) : "r"(wa + OFF_WL));
            }
            #pragma unroll
            for (int i = 0; i < 7; i++) {
                MMA_BF16(acc[i], ah[0], ah[1], ah[2], ah[3], wh[i][0], wh[i][1]);
                MMA_BF16(acc[i], al[0], al[1], al[2], al[3], wh[i][0], wh[i][1]);
                MMA_BF16(acc[i], ah[0], ah[1], ah[2], ah[3], wl[i][0], wl[i][1]);
            }
        }

        // ---- gate exchange + in-register activations ----
        #pragma unroll
        for (int i = 0; i < 7; i++) {
            if (tv[i]) {
                float s0 = __shfl_xor_sync(0xffffffffu, acc[i][0], 1);
                float s1 = __shfl_xor_sync(0xffffffffu, acc[i][1], 1);
                float s2 = __shfl_xor_sync(0xffffffffu, acc[i][2], 1);
                float s3 = __shfl_xor_sync(0xffffffffu, acc[i][3], 1);
                bool odd = (t4 & 1);
                float gi = odd ? s2 : acc[i][0];
                float gf = odd ? s3 : acc[i][1];
                float gg = odd ? acc[i][2] : s0;
                float go = odd ? acc[i][3] : s1;
                float cv = fsig(gf) * cst[i] + fsig(gi) * ftanh_(gg);
                cst[i] = cv;
                float h = fsig(go) * ftanh_(cv);
                __nv_bfloat16 hh = __float2bfloat16(h);
                __nv_bfloat16 hl = __float2bfloat16(h - __bfloat162float(hh));
                int bu = g + (odd ? 8 : 0);
                int ju = 2 * tl[i] + (t4 >> 1);
                uint32_t off = OFF_A + nxt * ABUF + bu * KSB + ju * 2;
                *(__nv_bfloat16*)(smc + off) = hh;
                *(__nv_bfloat16*)(smc + off + 3840) = hl;
                if (mode == 0) {
                    size_t rr = ((size_t)tg * B + b0 + bu) * KPAD + dir * 100 + ju;
                    g_Ah[rr] = hh; g_Al[rr] = hl;
                    if (tg == T - 1)
                        g_h0s[(size_t)(b0 + bu) * 200 + dir * 100 + ju] = h;
                } else if (ts == T - 1) {
                    g_h1f[(size_t)(b0 + bu) * 100 + ju] = h;
                }
            }
        }
        // stage next x into buf nxt
        if (mode == 0 && tid < 16 * INP && ts + 1 < T) {
            int bb = tid / INP, d = tid - (tid / INP) * INP;
            __nv_bfloat16 hb = __float2bfloat16(xv);
            __nv_bfloat16 lb = __float2bfloat16(xv - __bfloat162float(hb));
            *(__nv_bfloat16*)(smc + OFF_A + nxt * ABUF + bb * KSB + (100 + d) * 2) = hb;
            *(__nv_bfloat16*)(smc + OFF_A + nxt * ABUF + 3840 + bb * KSB + (100 + d) * 2) = lb;
        }
        __syncthreads();
    }
}

// ============================================================================
// conv_b: W_ih_l1f -> bf16 hi/lo, rows gate-interleaved (n' = j*4+gate).
// ============================================================================
__global__ void conv_b_kernel(const float* __restrict__ wih)
{
    int i = blockIdx.x * 256 + threadIdx.x;
    if (i < 400 * 200) {
        int r = i / 200, k = i - r * 200;
        int np = (r % 100) * 4 + r / 100;
        float w = wih[i];
        __nv_bfloat16 hb = __float2bfloat16(w);
        __nv_bfloat16 lb = __float2bfloat16(w - __bfloat162float(hb));
        g_Bh[np * KPAD + k] = hb;
        g_Bl[np * KPAD + k] = lb;
    }
}

// ============================================================================
// xg1 GEMM via mma.sync bf16 (split hi/lo, 3 products); output cols are
// gate-interleaved (B rows were permuted); bias permuted to match.
// ============================================================================
__global__ void __launch_bounds__(256, 2) gemm_xg1_mma(
    const float* __restrict__ bih, const float* __restrict__ bhh)
{
    __shared__ __align__(16) __nv_bfloat16 Asm[2][128][24];
    __shared__ __align__(16) __nv_bfloat16 Bsm[2][80][24];
    __shared__ float bsm[400];

    const int tid  = threadIdx.x;
    const int wid  = tid >> 5;
    const int lane = tid & 31;
    const int m0   = blockIdx.x * 128;
    const int n0   = blockIdx.y * 80;
    const int wm   = (wid >> 1) * 32;
    const int wn   = (wid & 1) * 40;

    for (int i = tid; i < 400; i += 256) {
        int r = (i & 3) * 100 + (i >> 2);
        bsm[i] = bih[r] + bhh[r];
    }

    float acc[2][5][4];
    #pragma unroll
    for (int mt = 0; mt < 2; mt++)
        #pragma unroll
        for (int nt = 0; nt < 5; nt++)
            #pragma unroll
            for (int e = 0; e < 4; e++) acc[mt][nt][e] = 0.f;

    const int arow = tid >> 1, ahalf = tid & 1;
    const int brow = tid >> 1, bhalf = tid & 1;

    uint4 areg = *(const uint4*)(g_Ah + (size_t)(m0 + arow) * KPAD + ahalf * 8);
    uint4 breg = make_uint4(0, 0, 0, 0);
    if (tid < 160) breg = *(const uint4*)(g_Bh + (size_t)(n0 + brow) * KPAD + bhalf * 8);
    *(uint4*)&Asm[0][arow][ahalf * 8] = areg;
    if (tid < 160) *(uint4*)&Bsm[0][brow][bhalf * 8] = breg;
    __syncthreads();

    const uint32_t a_base = smem_u32(&Asm[0][0][0]);
    const uint32_t b_base = smem_u32(&Bsm[0][0][0]);

    for (int it = 0; it < 39; it++) {
        const int cur = it & 1, nxt = cur ^ 1;
        if (it < 38) {
            const int it2 = it + 1;
            const int seg = it2 / 13, kc = it2 - seg * 13;
            const __nv_bfloat16* Ap = (seg == 1) ? g_Al : g_Ah;
            const __nv_bfloat16* Bp = (seg == 2) ? g_Bl : g_Bh;
            areg = *(const uint4*)(Ap + (size_t)(m0 + arow) * KPAD + kc * 16 + ahalf * 8);
            if (tid < 160)
                breg = *(const uint4*)(Bp + (size_t)(n0 + brow) * KPAD + kc * 16 + bhalf * 8);
        }
        const uint32_t abuf = a_base + cur * (128 * 24 * 2);
        const uint32_t bbuf = b_base + cur * (80 * 24 * 2);

        uint32_t af[2][4];
        #pragma unroll
        for (int mt = 0; mt < 2; mt++) {
            uint32_t addr = abuf + (wm + mt * 16 + (lane & 15)) * 48 + (lane >> 4) * 16;
            asm volatile("ldmatrix.sync.aligned.m8n8.x4.shared.b16 {%0,%1,%2,%3}, [%4];"
                : "=r"(af[mt][0]), "=r"(af[mt][1]), "=r"(af[mt][2]), "=r"(af[mt][3])
                : "r"(addr));
        }
        uint32_t bf[5][2];
        #pragma unroll
        for (int nt = 0; nt < 5; nt++) {
            uint32_t addr = bbuf + (wn + nt * 8 + (lane & 7)) * 48 + ((lane >> 3) & 1) * 16;
            asm volatile("ldmatrix.sync.aligned.m8n8.x2.shared.b16 {%0,%1}, [%2];"
                : "=r"(bf[nt][0]), "=r"(bf[nt][1]) : "r"(addr));
        }
        #pragma unroll
        for (int mt = 0; mt < 2; mt++)
            #pragma unroll
            for (int nt = 0; nt < 5; nt++) {
                MMA_BF16(acc[mt][nt], af[mt][0], af[mt][1], af[mt][2], af[mt][3],
                         bf[nt][0], bf[nt][1]);
            }
        if (it < 38) {
            *(uint4*)&Asm[nxt][arow][ahalf * 8] = areg;
            if (tid < 160) *(uint4*)&Bsm[nxt][brow][bhalf * 8] = breg;
        }
        __syncthreads();
    }

    const int gid = lane >> 2, t4 = lane & 3;
    #pragma unroll
    for (int mt = 0; mt < 2; mt++) {
        #pragma unroll
        for (int nt = 0; nt < 5; nt++) {
            int mrow = m0 + wm + mt * 16 + gid;
            int ncol = n0 + wn + nt * 8 + t4 * 2;
            float by = bsm[ncol + 1];
            float2 v0 = make_float2(acc[mt][nt][0] + bsm[ncol], acc[mt][nt][1] + by);
            float2 v1 = make_float2(acc[mt][nt][2] + bsm[ncol], acc[mt][nt][3] + by);
            *(float2*)&g_xg1[(size_t)mrow * 400 + ncol]       = v0;
            *(float2*)&g_xg1[(size_t)(mrow + 8) * 400 + ncol] = v1;
        }
    }
}

// ============================================================================
// lstm_final: layer1 backward single step (c0=0) + FC + softmax. (unchanged)
// ============================================================================
#define FN_SMEMF (30000 + 200*18 + 1600 + 300 + 600 + 4 + 48)

__global__ void __launch_bounds__(256, 1) lstm_final(
    const float* __restrict__ wih1b,
    const float* __restrict__ bih1b, const float* __restrict__ bhh1b,
    const float* __restrict__ fc_w,  const float* __restrict__ fc_b,
    float* __restrict__ out)
{
    extern __shared__ float sm[];
    float* wT   = sm;
    float* h0s  = sm + 30000;
    float* h1bs = sm + 33600;
    float* b3   = sm + 35200;
    float* fcw  = sm + 35500;
    float* fcb  = sm + 36100;
    float* lg   = sm + 36104;

    const int tid = threadIdx.x;
    const int b0 = blockIdx.x * 16;

    for (int i = tid; i < 16 * 200; i += 256) {
        int b = i / 200, k = i - b * 200;
        h0s[k * 18 + b] = g_h0s[(size_t)(b0 + b) * 200 + k];
    }
    for (int i = tid; i < 300; i += 256) {
        int g3 = i / 100, j = i - g3 * 100;
        int row = j + (g3 == 0 ? 0 : (g3 == 1 ? 200 : 300));
        b3[i] = bih1b[row] + bhh1b[row];
    }
    for (int i = tid; i < 600; i += 256) fcw[i] = fc_w[i];
    if (tid < 3) fcb[tid] = fc_b[tid];

    const int  jj  = tid & 127;
    const int  grp = tid >> 7;
    const bool act = (jj < H);

    u64 acc[4][3];
    #pragma unroll
    for (int p = 0; p < 4; p++)
        #pragma unroll
        for (int g = 0; g < 3; g++) acc[p][g] = pk2(0.f, 0.f);

    for (int kt = 0; kt < 2; kt++) {
        __syncthreads();
        for (int i = tid; i < 30000; i += 256) {
            int k = i % 100, j100 = i / 100;
            int grow = j100 + (j100 >= 100 ? 100 : 0);
            wT[k * 300 + j100] = wih1b[(size_t)grow * 200 + kt * 100 + k];
        }
        __syncthreads();
        if (act) {
            #pragma unroll 2
            for (int k = 0; k < 100; k++) {
                const float* wr = wT + k * 300 + jj;
                u64 w0 = pk2(wr[0], wr[0]);
                u64 w1 = pk2(wr[100], wr[100]);
                u64 w2 = pk2(wr[200], wr[200]);
                const float* hb = h0s + (kt * 100 + k) * 18 + grp * 8;
                #pragma unroll
                for (int p = 0; p < 4; p++) {
                    u64 hv = *(const u64*)(hb + 2 * p);
                    acc[p][0] = ffma2(w0, hv, acc[p][0]);
                    acc[p][1] = ffma2(w1, hv, acc[p][1]);
                    acc[p][2] = ffma2(w2, hv, acc[p][2]);
                }
            }
        }
    }
    if (act) {
        #pragma unroll
        for (int p = 0; p < 4; p++) {
            float i0, i1, g0, g1, o0, o1;
            upk2(acc[p][0], i0, i1);
            upk2(acc[p][1], g0, g1);
            upk2(acc[p][2], o0, o1);
            float bi = b3[jj], bg = b3[100 + jj], bo = b3[200 + jj];
            i0 += bi; i1 += bi; g0 += bg; g1 += bg; o0 += bo; o1 += bo;
            float c0 = fsig(i0) * ftanh_(g0);
            float c1 = fsig(i1) * ftanh_(g1);
            int bl = grp * 8 + 2 * p;
            h1bs[bl * 100 + jj]       = fsig(o0) * ftanh_(c0);
            h1bs[(bl + 1) * 100 + jj] = fsig(o1) * ftanh_(c1);
        }
    }
    __syncthreads();
    if (tid < 48) {
        int b = tid / 3, cls = tid - b * 3;
        float a = fcb[cls];
        const float* h1f = g_h1f + (size_t)(b0 + b) * 100;
        #pragma unroll 4
        for (int j = 0; j < 100; j++) {
            a += h1f[j]            * fcw[cls * 200 + j];
            a += h1bs[b * 100 + j] * fcw[cls * 200 + 100 + j];
        }
        lg[tid] = a;
    }
    __syncthreads();
    if (tid < 16) {
        int b = tid;
        float l0 = lg[b * 3], l1 = lg[b * 3 + 1], l2 = lg[b * 3 + 2];
        float m = fmaxf(l0, fmaxf(l1, l2));
        float e0 = __expf(l0 - m), e1 = __expf(l1 - m), e2 = __expf(l2 - m);
        float s = 1.0f / (e0 + e1 + e2);
        out[(b0 + b) * 3 + 0] = e0 * s;
        out[(b0 + b) * 3 + 1] = e1 * s;
        out[(b0 + b) * 3 + 2] = e2 * s;
    }
}

// ============================================================================
extern "C" void kernel_launch(void* const* d_in, const int* in_sizes, int n_in,
                              void* d_out, int out_size)
{
    (void)in_sizes; (void)n_in; (void)out_size;
    const float* x     = (const float*)d_in[0];
    const float* wih0f = (const float*)d_in[1];
    const float* whh0f = (const float*)d_in[2];
    const float* bih0f = (const float*)d_in[3];
    const float* bhh0f = (const float*)d_in[4];
    const float* wih0b = (const float*)d_in[5];
    const float* whh0b = (const float*)d_in[6];
    const float* bih0b = (const float*)d_in[7];
    const float* bhh0b = (const float*)d_in[8];
    const float* wih1f = (const float*)d_in[9];
    const float* whh1f = (const float*)d_in[10];
    const float* bih1f = (const float*)d_in[11];
    const float* bhh1f = (const float*)d_in[12];
    const float* wih1b = (const float*)d_in[13];
    const float* bih1b = (const float*)d_in[15];
    const float* bhh1b = (const float*)d_in[16];
    const float* fcw   = (const float*)d_in[17];
    const float* fcb   = (const float*)d_in[18];
    float* out = (float*)d_out;

    float* xg1p; cudaGetSymbolAddress((void**)&xg1p, g_xg1);

    cudaFuncSetAttribute(lstm_rec_mma, cudaFuncAttributeMaxDynamicSharedMemorySize, RC_SMEM);
    cudaFuncSetAttribute(lstm_final,   cudaFuncAttributeMaxDynamicSharedMemorySize, FN_SMEMF * 4);

    conv_b_kernel<<<(400 * 200 + 255) / 256, 256>>>(wih1f);
    lstm_rec_mma<<<128, 256, RC_SMEM>>>(nullptr, x, whh0f, whh0b, wih0f, wih0b,
                                        bih0f, bhh0f, bih0b, bhh0b, 0);
    gemm_xg1_mma<<<dim3(1024, 5), 256>>>(bih1f, bhh1f);
    lstm_rec_mma<<<64, 256, RC_SMEM>>>(xg1p, nullptr, whh1f, whh1f, wih1f, wih1f,
                                       bih1f, bhh1f, bih1f, bhh1f, 1);
    lstm_final<<<64, 256, FN_SMEMF * 4>>>(wih1b, bih1b, bhh1b, fcw, fcb, out);
}

// round 10
// speedup vs baseline: 1.2474x; 1.0027x over previous
#include <cuda_runtime.h>
#include <cuda_bf16.h>
#include <cstdint>

#define B 1024
#define T 128
#define INP 5
#define H 100
#define G4 400
#define MTOT (B*T)
#define KPAD 208

// ---------------- scratch (device globals; no runtime allocation) ----------
__device__ float g_h0s[B * 2 * H];            // [b][200] h0 at t=T-1
__device__ float g_xg1[(size_t)MTOT * G4];    // [t*B+b][n'] layer1-fwd gates (+bias), gate-interleaved
__device__ float g_h1f[B * H];
__device__ __nv_bfloat16 g_Ah[(size_t)MTOT * KPAD];   // h0 hi, [t*B+b][k]; cols 200..207 = 0
__device__ __nv_bfloat16 g_Al[(size_t)MTOT * KPAD];
__device__ __nv_bfloat16 g_Bh[400 * KPAD];            // W_ih_l1f rows gate-interleaved
__device__ __nv_bfloat16 g_Bl[400 * KPAD];

typedef unsigned long long u64;

__device__ __forceinline__ u64 pk2(float a, float b) {
    u64 r; asm("mov.b64 %0, {%1,%2};" : "=l"(r) : "f"(a), "f"(b)); return r;
}
__device__ __forceinline__ void upk2(u64 v, float& a, float& b) {
    asm("mov.b64 {%0,%1}, %2;" : "=f"(a), "=f"(b) : "l"(v));
}
__device__ __forceinline__ u64 ffma2(u64 a, u64 b, u64 c) {
    asm("fma.rn.f32x2 %0, %1, %2, %0;" : "+l"(c) : "l"(a), "l"(b)); return c;
}
__device__ __forceinline__ float fsig(float x) {
    float e; asm("ex2.approx.f32 %0, %1;" : "=f"(e) : "f"(x * -1.4426950408889634f));
    float r; asm("rcp.approx.f32 %0, %1;" : "=f"(r) : "f"(e + 1.0f));
    return r;
}
__device__ __forceinline__ float ftanh_(float x) {
    float e; asm("ex2.approx.f32 %0, %1;" : "=f"(e) : "f"(x * -2.885390081777927f));
    float r; asm("rcp.approx.f32 %0, %1;" : "=f"(r) : "f"(e + 1.0f));
    return fmaf(2.0f, r, -1.0f);
}
__device__ __forceinline__ uint32_t smem_u32(const void* p) {
    uint32_t a;
    asm("{ .reg .u64 t; cvta.to.shared.u64 t, %1; cvt.u32.u64 %0, t; }" : "=r"(a) : "l"(p));
    return a;
}

#define MMA_BF16(ac, a0,a1,a2,a3, b0,b1) \
    asm volatile("mma.sync.aligned.m16n8k16.row.col.f32.bf16.bf16.f32 " \
        "{%0,%1,%2,%3}, {%4,%5,%6,%7}, {%8,%9}, {%0,%1,%2,%3};" \
        : "+f"((ac)[0]), "+f"((ac)[1]), "+f"((ac)[2]), "+f"((ac)[3]) \
        : "r"(a0), "r"(a1), "r"(a2), "r"(a3), "r"(b0), "r"(b1))

// ============================================================================
// UNIFIED TENSOR-CORE RECURRENCE, gate-interleaved (n' = j*4 + gate).
// 16 batches/CTA, 512 thr / 16 warps, 4 n-tile slots per warp (dummies
// clamped to tile 0, results discarded). Per step ONE barrier:
// MMA (x-proj folded into k=100..104, product-outer ordering) ->
// shfl.bfly gate exchange -> in-register activations -> h into
// double-buffered A staging.
// mode 0: layer0 (grid 128), emits g_Ah/g_Al + g_h0s. mode 1: layer1 fwd
// (grid 64), acc init from g_xg1, emits g_h1f.
// SMEM: Wh[400][120] | Wl | A bufs x2 (Ah[16][120] + Al)
// ============================================================================
#define KSB     240
#define OFF_WL  96000
#define OFF_A   192000
#define ABUF    7680
#define RC_SMEM 207360
#define NTHR    512

__global__ void __launch_bounds__(NTHR, 1) lstm_rec_mma(
    const float* __restrict__ xg,
    const float* __restrict__ x,
    const float* __restrict__ whf, const float* __restrict__ whb,
    const float* __restrict__ wihf, const float* __restrict__ wihb,
    const float* __restrict__ bihf, const float* __restrict__ bhhf,
    const float* __restrict__ bihb, const float* __restrict__ bhhb,
    int mode)
{
    extern __shared__ char smc[];
    const uint32_t sb = smem_u32(smc);
    const int tid = threadIdx.x, wid = tid >> 5, lane = tid & 31;
    const int g = lane >> 2, t4 = lane & 3;
    const int dir = (mode == 0) ? (int)(blockIdx.x >> 6) : 0;
    const int b0  = (mode == 0) ? (int)(blockIdx.x & 63) * 16 : (int)blockIdx.x * 16;
    const float* wp  = dir ? whb  : whf;
    const float* wip = dir ? wihb : wihf;
    const float* bi_ = dir ? bihb : bihf;
    const float* bh_ = dir ? bhhb : bhhf;

    // zero everything (W pads, A pads, h=0 initial state)
    for (int i = tid; i < (RC_SMEM >> 4); i += NTHR)
        ((uint4*)smc)[i] = make_uint4(0, 0, 0, 0);
    __syncthreads();
    // W fill: row n' = j*4+gate <- orig row gate*100+j ; k 0..99 = Whh
    for (int i = tid; i < 400 * 100; i += NTHR) {
        int r = i / 100, k = i - r * 100;
        int np = (r % 100) * 4 + r / 100;
        float w = wp[i];
        __nv_bfloat16 hb = __float2bfloat16(w);
        __nv_bfloat16 lb = __float2bfloat16(w - __bfloat162float(hb));
        *(__nv_bfloat16*)(smc + np * KSB + k * 2) = hb;
        *(__nv_bfloat16*)(smc + OFF_WL + np * KSB + k * 2) = lb;
    }
    if (mode == 0) {
        for (int i = tid; i < 400 * INP; i += NTHR) {
            int r = i / INP, d = i - r * INP;
            int np = (r % 100) * 4 + r / 100;
            float w = wip[i];
            __nv_bfloat16 hb = __float2bfloat16(w);
            __nv_bfloat16 lb = __float2bfloat16(w - __bfloat162float(hb));
            *(__nv_bfloat16*)(smc + np * KSB + (100 + d) * 2) = hb;
            *(__nv_bfloat16*)(smc + OFF_WL + np * KSB + (100 + d) * 2) = lb;
        }
        if (tid < 16 * INP) {
            int bb = tid / INP, d = tid - (tid / INP) * INP;
            int tg0 = dir ? (T - 1) : 0;
            float xv = x[((size_t)(b0 + bb) * T + tg0) * INP + d];
            __nv_bfloat16 hb = __float2bfloat16(xv);
            __nv_bfloat16 lb = __float2bfloat16(xv - __bfloat162float(hb));
            *(__nv_bfloat16*)(smc + OFF_A + bb * KSB + (100 + d) * 2) = hb;
            *(__nv_bfloat16*)(smc + OFF_A + 3840 + bb * KSB + (100 + d) * 2) = lb;
        }
    }

    // 4 slots/warp: tile = wid + 16*i, valid if < 50 (dummies -> tile 0)
    int  tl[4]; bool tv[4];
    float br[4][2];
    #pragma unroll
    for (int i = 0; i < 4; i++) {
        int t = wid + 16 * i;
        tv[i] = (t < 50); tl[i] = tv[i] ? t : 0;
        br[i][0] = br[i][1] = 0.f;
        if (mode == 0 && tv[i]) {
            int np = t * 8 + 2 * t4;
            int r0 = (np & 3) * 100 + (np >> 2);
            int r1 = ((np + 1) & 3) * 100 + ((np + 1) >> 2);
            br[i][0] = bi_[r0] + bh_[r0];
            br[i][1] = bi_[r1] + bh_[r1];
        }
    }
    float cst[4];
    #pragma unroll
    for (int i = 0; i < 4; i++) cst[i] = 0.f;

    float xp[4][4];
    if (mode == 1) {
        #pragma unroll
        for (int i = 0; i < 4; i++) {
            xp[i][0] = xp[i][1] = xp[i][2] = xp[i][3] = 0.f;
            if (tv[i]) {
                const float* p0 = xg + (size_t)(b0 + g) * 400 + tl[i] * 8 + 2 * t4;
                float2 v0 = *(const float2*)p0;
                float2 v1 = *(const float2*)(p0 + 3200);
                xp[i][0] = v0.x; xp[i][1] = v0.y; xp[i][2] = v1.x; xp[i][3] = v1.y;
            }
        }
    }
    __syncthreads();

    for (int ts = 0; ts < T; ts++) {
        const int cur = ts & 1, nxt = cur ^ 1;
        const int tg = dir ? (T - 1 - ts) : ts;

        float acc[4][4];
        if (mode == 0) {
            #pragma unroll
            for (int i = 0; i < 4; i++) {
                acc[i][0] = br[i][0]; acc[i][1] = br[i][1];
                acc[i][2] = br[i][0]; acc[i][3] = br[i][1];
            }
        } else {
            #pragma unroll
            for (int i = 0; i < 4; i++) {
                acc[i][0] = xp[i][0]; acc[i][1] = xp[i][1];
                acc[i][2] = xp[i][2]; acc[i][3] = xp[i][3];
            }
            if (ts + 1 < T) {
                #pragma unroll
                for (int i = 0; i < 4; i++) {
                    if (tv[i]) {
                        const float* p0 = xg + ((size_t)(ts + 1) * B + b0 + g) * 400 + tl[i] * 8 + 2 * t4;
                        float2 v0 = *(const float2*)p0;
                        float2 v1 = *(const float2*)(p0 + 3200);
                        xp[i][0] = v0.x; xp[i][1] = v0.y; xp[i][2] = v1.x; xp[i][3] = v1.y;
                    }
                }
            }
        }
        float xv = 0.f;
        if (mode == 0 && tid < 16 * INP && ts + 1 < T) {
            int bb = tid / INP, d = tid - (tid / INP) * INP;
            int tgn = dir ? (tg - 1) : (tg + 1);
            xv = x[((size_t)(b0 + bb) * T + tgn) * INP + d];
        }

        // ---- MMA: 7 k-chunks x 4 slots x 3 split products (product-outer) ----
        const uint32_t aBase = sb + OFF_A + cur * ABUF;
        #pragma unroll
        for (int kc = 0; kc < 7; kc++) {
            uint32_t ah[4], al[4];
            uint32_t aa = aBase + (lane & 15) * KSB + (lane >> 4) * 16 + kc * 32;
            asm volatile("ldmatrix.sync.aligned.m8n8.x4.shared.b16 {%0,%1,%2,%3}, [%4];"
                : "=r"(ah[0]), "=r"(ah[1]), "=r"(ah[2]), "=r"(ah[3]) : "r"(aa));
            asm volatile("ldmatrix.sync.aligned.m8n8.x4.shared.b16 {%0,%1,%2,%3}, [%4];"
                : "=r"(al[0]), "=r"(al[1]), "=r"(al[2]), "=r"(al[3]) : "r"(aa + 3840));

            uint32_t wh[4][2], wl[4][2];
            #pragma unroll
            for (int p = 0; p < 2; p++) {
                int m = lane >> 3;
                int tt = tl[2 * p + (m >> 1)];
                uint32_t wa = sb + (8 * tt + (lane & 7)) * KSB + (m & 1) * 16 + kc * 32;
                asm volatile("ldmatrix.sync.aligned.m8n8.x4.shared.b16 {%0,%1,%2,%3}, [%4];"
                    : "=r"(wh[2*p][0]), "=r"(wh[2*p][1]), "=r"(wh[2*p+1][0]), "=r"(wh[2*p+1][1])
                    : "r"(wa));
                asm volatile("ldmatrix.sync.aligned.m8n8.x4.shared.b16 {%0,%1,%2,%3}, [%4];"
                    : "=r"(wl[2*p][0]), "=r"(wl[2*p][1]), "=r"(wl[2*p+1][0]), "=r"(wl[2*p+1][1])
                    : "r"(wa + OFF_WL));
            }
            // product-outer: dependent MMAs on one acc are 4 apart
            #pragma unroll
            for (int i = 0; i < 4; i++)
                MMA_BF16(acc[i], ah[0], ah[1], ah[2], ah[3], wh[i][0], wh[i][1]);
            #pragma unroll
            for (int i = 0; i < 4; i++)
                MMA_BF16(acc[i], al[0], al[1], al[2], al[3], wh[i][0], wh[i][1]);
            #pragma unroll
            for (int i = 0; i < 4; i++)
                MMA_BF16(acc[i], ah[0], ah[1], ah[2], ah[3], wl[i][0], wl[i][1]);
        }

        // ---- gate exchange + in-register activations ----
        #pragma unroll
        for (int i = 0; i < 4; i++) {
            if (tv[i]) {
                float s0 = __shfl_xor_sync(0xffffffffu, acc[i][0], 1);
                float s1 = __shfl_xor_sync(0xffffffffu, acc[i][1], 1);
                float s2 = __shfl_xor_sync(0xffffffffu, acc[i][2], 1);
                float s3 = __shfl_xor_sync(0xffffffffu, acc[i][3], 1);
                bool odd = (t4 & 1);
                float gi = odd ? s2 : acc[i][0];
                float gf = odd ? s3 : acc[i][1];
                float gg = odd ? acc[i][2] : s0;
                float go = odd ? acc[i][3] : s1;
                float cv = fsig(gf) * cst[i] + fsig(gi) * ftanh_(gg);
                cst[i] = cv;
                float h = fsig(go) * ftanh_(cv);
                __nv_bfloat16 hh = __float2bfloat16(h);
                __nv_bfloat16 hl = __float2bfloat16(h - __bfloat162float(hh));
                int bu = g + (odd ? 8 : 0);
                int ju = 2 * tl[i] + (t4 >> 1);
                uint32_t off = OFF_A + nxt * ABUF + bu * KSB + ju * 2;
                *(__nv_bfloat16*)(smc + off) = hh;
                *(__nv_bfloat16*)(smc + off + 3840) = hl;
                if (mode == 0) {
                    size_t rr = ((size_t)tg * B + b0 + bu) * KPAD + dir * 100 + ju;
                    g_Ah[rr] = hh; g_Al[rr] = hl;
                    if (tg == T - 1)
                        g_h0s[(size_t)(b0 + bu) * 200 + dir * 100 + ju] = h;
                } else if (ts == T - 1) {
                    g_h1f[(size_t)(b0 + bu) * 100 + ju] = h;
                }
            }
        }
        if (mode == 0 && tid < 16 * INP && ts + 1 < T) {
            int bb = tid / INP, d = tid - (tid / INP) * INP;
            __nv_bfloat16 hb = __float2bfloat16(xv);
            __nv_bfloat16 lb = __float2bfloat16(xv - __bfloat162float(hb));
            *(__nv_bfloat16*)(smc + OFF_A + nxt * ABUF + bb * KSB + (100 + d) * 2) = hb;
            *(__nv_bfloat16*)(smc + OFF_A + nxt * ABUF + 3840 + bb * KSB + (100 + d) * 2) = lb;
        }
        __syncthreads();
    }
}

// ============================================================================
// conv_b: W_ih_l1f -> bf16 hi/lo, rows gate-interleaved (n' = j*4+gate).
// ============================================================================
__global__ void conv_b_kernel(const float* __restrict__ wih)
{
    int i = blockIdx.x * 256 + threadIdx.x;
    if (i < 400 * 200) {
        int r = i / 200, k = i - r * 200;
        int np = (r % 100) * 4 + r / 100;
        float w = wih[i];
        __nv_bfloat16 hb = __float2bfloat16(w);
        __nv_bfloat16 lb = __float2bfloat16(w - __bfloat162float(hb));
        g_Bh[np * KPAD + k] = hb;
        g_Bl[np * KPAD + k] = lb;
    }
}

// ============================================================================
// xg1 GEMM via mma.sync bf16 (split hi/lo, 3 products); gate-interleaved
// output. grid (5, 1024): the 5 CTAs sharing an A m-tile are launch-adjacent
// so A re-reads hit L2.
// ============================================================================
__global__ void __launch_bounds__(256, 2) gemm_xg1_mma(
    const float* __restrict__ bih, const float* __restrict__ bhh)
{
    __shared__ __align__(16) __nv_bfloat16 Asm[2][128][24];
    __shared__ __align__(16) __nv_bfloat16 Bsm[2][80][24];
    __shared__ float bsm[400];

    const int tid  = threadIdx.x;
    const int wid  = tid >> 5;
    const int lane = tid & 31;
    const int n0   = blockIdx.x * 80;
    const int m0   = blockIdx.y * 128;
    const int wm   = (wid >> 1) * 32;
    const int wn   = (wid & 1) * 40;

    for (int i = tid; i < 400; i += 256) {
        int r = (i & 3) * 100 + (i >> 2);
        bsm[i] = bih[r] + bhh[r];
    }

    float acc[2][5][4];
    #pragma unroll
    for (int mt = 0; mt < 2; mt++)
        #pragma unroll
        for (int nt = 0; nt < 5; nt++)
            #pragma unroll
            for (int e = 0; e < 4; e++) acc[mt][nt][e] = 0.f;

    const int arow = tid >> 1, ahalf = tid & 1;
    const int brow = tid >> 1, bhalf = tid & 1;

    uint4 areg = *(const uint4*)(g_Ah + (size_t)(m0 + arow) * KPAD + ahalf * 8);
    uint4 breg = make_uint4(0, 0, 0, 0);
    if (tid < 160) breg = *(const uint4*)(g_Bh + (size_t)(n0 + brow) * KPAD + bhalf * 8);
    *(uint4*)&Asm[0][arow][ahalf * 8] = areg;
    if (tid < 160) *(uint4*)&Bsm[0][brow][bhalf * 8] = breg;
    __syncthreads();

    const uint32_t a_base = smem_u32(&Asm[0][0][0]);
    const uint32_t b_base = smem_u32(&Bsm[0][0][0]);

    for (int it = 0; it < 39; it++) {
        const int cur = it & 1, nxt = cur ^ 1;
        if (it < 38) {
            const int it2 = it + 1;
            const int seg = it2 / 13, kc = it2 - seg * 13;
            const __nv_bfloat16* Ap = (seg == 1) ? g_Al : g_Ah;
            const __nv_bfloat16* Bp = (seg == 2) ? g_Bl : g_Bh;
            areg = *(const uint4*)(Ap + (size_t)(m0 + arow) * KPAD + kc * 16 + ahalf * 8);
            if (tid < 160)
                breg = *(const uint4*)(Bp + (size_t)(n0 + brow) * KPAD + kc * 16 + bhalf * 8);
        }
        const uint32_t abuf = a_base + cur * (128 * 24 * 2);
        const uint32_t bbuf = b_base + cur * (80 * 24 * 2);

        uint32_t af[2][4];
        #pragma unroll
        for (int mt = 0; mt < 2; mt++) {
            uint32_t addr = abuf + (wm + mt * 16 + (lane & 15)) * 48 + (lane >> 4) * 16;
            asm volatile("ldmatrix.sync.aligned.m8n8.x4.shared.b16 {%0,%1,%2,%3}, [%4];"
                : "=r"(af[mt][0]), "=r"(af[mt][1]), "=r"(af[mt][2]), "=r"(af[mt][3])
                : "r"(addr));
        }
        uint32_t bf[5][2];
        #pragma unroll
        for (int nt = 0; nt < 5; nt++) {
            uint32_t addr = bbuf + (wn + nt * 8 + (lane & 7)) * 48 + ((lane >> 3) & 1) * 16;
            asm volatile("ldmatrix.sync.aligned.m8n8.x2.shared.b16 {%0,%1}, [%2];"
                : "=r"(bf[nt][0]), "=r"(bf[nt][1]) : "r"(addr));
        }
        #pragma unroll
        for (int mt = 0; mt < 2; mt++)
            #pragma unroll
            for (int nt = 0; nt < 5; nt++) {
                MMA_BF16(acc[mt][nt], af[mt][0], af[mt][1], af[mt][2], af[mt][3],
                         bf[nt][0], bf[nt][1]);
            }
        if (it < 38) {
            *(uint4*)&Asm[nxt][arow][ahalf * 8] = areg;
            if (tid < 160) *(uint4*)&Bsm[nxt][brow][bhalf * 8] = breg;
        }
        __syncthreads();
    }

    const int gid = lane >> 2, t4 = lane & 3;
    #pragma unroll
    for (int mt = 0; mt < 2; mt++) {
        #pragma unroll
        for (int nt = 0; nt < 5; nt++) {
            int mrow = m0 + wm + mt * 16 + gid;
            int ncol = n0 + wn + nt * 8 + t4 * 2;
            float by = bsm[ncol + 1];
            float2 v0 = make_float2(acc[mt][nt][0] + bsm[ncol], acc[mt][nt][1] + by);
            float2 v1 = make_float2(acc[mt][nt][2] + bsm[ncol], acc[mt][nt][3] + by);
            *(float2*)&g_xg1[(size_t)mrow * 400 + ncol]       = v0;
            *(float2*)&g_xg1[(size_t)(mrow + 8) * 400 + ncol] = v1;
        }
    }
}

// ============================================================================
// lstm_final: layer1 backward single step (c0=0) + FC + softmax. (unchanged)
// ============================================================================
#define FN_SMEMF (30000 + 200*18 + 1600 + 300 + 600 + 4 + 48)

__global__ void __launch_bounds__(256, 1) lstm_final(
    const float* __restrict__ wih1b,
    const float* __restrict__ bih1b, const float* __restrict__ bhh1b,
    const float* __restrict__ fc_w,  const float* __restrict__ fc_b,
    float* __restrict__ out)
{
    extern __shared__ float sm[];
    float* wT   = sm;
    float* h0s  = sm + 30000;
    float* h1bs = sm + 33600;
    float* b3   = sm + 35200;
    float* fcw  = sm + 35500;
    float* fcb  = sm + 36100;
    float* lg   = sm + 36104;

    const int tid = threadIdx.x;
    const int b0 = blockIdx.x * 16;

    for (int i = tid; i < 16 * 200; i += 256) {
        int b = i / 200, k = i - b * 200;
        h0s[k * 18 + b] = g_h0s[(size_t)(b0 + b) * 200 + k];
    }
    for (int i = tid; i < 300; i += 256) {
        int g3 = i / 100, j = i - g3 * 100;
        int row = j + (g3 == 0 ? 0 : (g3 == 1 ? 200 : 300));
        b3[i] = bih1b[row] + bhh1b[row];
    }
    for (int i = tid; i < 600; i += 256) fcw[i] = fc_w[i];
    if (tid < 3) fcb[tid] = fc_b[tid];

    const int  jj  = tid & 127;
    const int  grp = tid >> 7;
    const bool act = (jj < H);

    u64 acc[4][3];
    #pragma unroll
    for (int p = 0; p < 4; p++)
        #pragma unroll
        for (int g = 0; g < 3; g++) acc[p][g] = pk2(0.f, 0.f);

    for (int kt = 0; kt < 2; kt++) {
        __syncthreads();
        for (int i = tid; i < 30000; i += 256) {
            int k = i % 100, j100 = i / 100;
            int grow = j100 + (j100 >= 100 ? 100 : 0);
            wT[k * 300 + j100] = wih1b[(size_t)grow * 200 + kt * 100 + k];
        }
        __syncthreads();
        if (act) {
            #pragma unroll 2
            for (int k = 0; k < 100; k++) {
                const float* wr = wT + k * 300 + jj;
                u64 w0 = pk2(wr[0], wr[0]);
                u64 w1 = pk2(wr[100], wr[100]);
                u64 w2 = pk2(wr[200], wr[200]);
                const float* hb = h0s + (kt * 100 + k) * 18 + grp * 8;
                #pragma unroll
                for (int p = 0; p < 4; p++) {
                    u64 hv = *(const u64*)(hb + 2 * p);
                    acc[p][0] = ffma2(w0, hv, acc[p][0]);
                    acc[p][1] = ffma2(w1, hv, acc[p][1]);
                    acc[p][2] = ffma2(w2, hv, acc[p][2]);
                }
            }
        }
    }
    if (act) {
        #pragma unroll
        for (int p = 0; p < 4; p++) {
            float i0, i1, g0, g1, o0, o1;
            upk2(acc[p][0], i0, i1);
            upk2(acc[p][1], g0, g1);
            upk2(acc[p][2], o0, o1);
            float bi = b3[jj], bg = b3[100 + jj], bo = b3[200 + jj];
            i0 += bi; i1 += bi; g0 += bg; g1 += bg; o0 += bo; o1 += bo;
            float c0 = fsig(i0) * ftanh_(g0);
            float c1 = fsig(i1) * ftanh_(g1);
            int bl = grp * 8 + 2 * p;
            h1bs[bl * 100 + jj]       = fsig(o0) * ftanh_(c0);
            h1bs[(bl + 1) * 100 + jj] = fsig(o1) * ftanh_(c1);
        }
    }
    __syncthreads();
    if (tid < 48) {
        int b = tid / 3, cls = tid - b * 3;
        float a = fcb[cls];
        const float* h1f = g_h1f + (size_t)(b0 + b) * 100;
        #pragma unroll 4
        for (int j = 0; j < 100; j++) {
            a += h1f[j]            * fcw[cls * 200 + j];
            a += h1bs[b * 100 + j] * fcw[cls * 200 + 100 + j];
        }
        lg[tid] = a;
    }
    __syncthreads();
    if (tid < 16) {
        int b = tid;
        float l0 = lg[b * 3], l1 = lg[b * 3 + 1], l2 = lg[b * 3 + 2];
        float m = fmaxf(l0, fmaxf(l1, l2));
        float e0 = __expf(l0 - m), e1 = __expf(l1 - m), e2 = __expf(l2 - m);
        float s = 1.0f / (e0 + e1 + e2);
        out[(b0 + b) * 3 + 0] = e0 * s;
        out[(b0 + b) * 3 + 1] = e1 * s;
        out[(b0 + b) * 3 + 2] = e2 * s;
    }
}

// ============================================================================
extern "C" void kernel_launch(void* const* d_in, const int* in_sizes, int n_in,
                              void* d_out, int out_size)
{
    (void)in_sizes; (void)n_in; (void)out_size;
    const float* x     = (const float*)d_in[0];
    const float* wih0f = (const float*)d_in[1];
    const float* whh0f = (const float*)d_in[2];
    const float* bih0f = (const float*)d_in[3];
    const float* bhh0f = (const float*)d_in[4];
    const float* wih0b = (const float*)d_in[5];
    const float* whh0b = (const float*)d_in[6];
    const float* bih0b = (const float*)d_in[7];
    const float* bhh0b = (const float*)d_in[8];
    const float* wih1f = (const float*)d_in[9];
    const float* whh1f = (const float*)d_in[10];
    const float* bih1f = (const float*)d_in[11];
    const float* bhh1f = (const float*)d_in[12];
    const float* wih1b = (const float*)d_in[13];
    const float* bih1b = (const float*)d_in[15];
    const float* bhh1b = (const float*)d_in[16];
    const float* fcw   = (const float*)d_in[17];
    const float* fcb   = (const float*)d_in[18];
    float* out = (float*)d_out;

    float* xg1p; cudaGetSymbolAddress((void**)&xg1p, g_xg1);

    cudaFuncSetAttribute(lstm_rec_mma, cudaFuncAttributeMaxDynamicSharedMemorySize, RC_SMEM);
    cudaFuncSetAttribute(lstm_final,   cudaFuncAttributeMaxDynamicSharedMemorySize, FN_SMEMF * 4);

    conv_b_kernel<<<(400 * 200 + 255) / 256, 256>>>(wih1f);
    lstm_rec_mma<<<128, NTHR, RC_SMEM>>>(nullptr, x, whh0f, whh0b, wih0f, wih0b,
                                         bih0f, bhh0f, bih0b, bhh0b, 0);
    gemm_xg1_mma<<<dim3(5, 1024), 256>>>(bih1f, bhh1f);
    lstm_rec_mma<<<64, NTHR, RC_SMEM>>>(xg1p, nullptr, whh1f, whh1f, wih1f, wih1f,
                                        bih1f, bhh1f, bih1f, bhh1f, 1);
    lstm_final<<<64, 256, FN_SMEMF * 4>>>(wih1b, bih1b, bhh1b, fcw, fcb, out);
}